// round 4
// baseline (speedup 1.0000x reference)
#include <cuda_runtime.h>
#include <cuda_bf16.h>
#include <cstdint>

// Problem dims
#define BB 1024
#define TT 100
#define MM 128
#define HH 128
#define PP 128
#define CC 32
#define GG 512   // 4H

// ---------------- device scratch (static, no allocation) ----------------
__device__ float g_alpha[BB * MM];                 // 512 KB
__device__ float g_G1[BB * TT * GG];               // 209.7 MB  gates input (incl biases)
__device__ float g_Xenc[BB * TT * HH];             // 52.4 MB
__device__ float g_preX[BB * TT * HH];             // 52.4 MB   X_enc @ W1x^T + b1
__device__ float g_h[BB * HH];
__device__ float g_c[BB * HH];
__device__ float g_d[BB * PP];
__device__ float g_cc[BB * PP];
__device__ float g_u[BB * HH];
__device__ float g_ctx[BB * HH];
__device__ float g_y[BB];
__device__ float g_encWhhT[HH * GG];               // [k][g]
__device__ float g_decWhhT[PP * GG];
__device__ float g_encWihT[MM * GG];
__device__ float g_W1dcT[256 * HH];                // [k][h], k over (d,c)
__device__ float g_W1xT[HH * HH];                  // [k][h]
__device__ float g_encBias[GG];
__device__ float g_decBias[GG];

// ---------------- helpers ----------------
__device__ __forceinline__ float sigm(float x) {
    return 1.0f / (1.0f + __expf(-x));
}
__device__ __forceinline__ float tanh_s(float x) {   // safe accurate-ish tanh
    float a = fabsf(x);
    float e = __expf(-2.0f * a);
    float r = (1.0f - e) / (1.0f + e);
    return copysignf(r, x);
}
__device__ __forceinline__ float tanh_fast(float x) { // MUFU.TANH
    float y;
    asm("tanh.approx.f32 %0, %1;" : "=f"(y) : "f"(x));
    return y;
}

// ---------------- zero init of recurrent states ----------------
__global__ void zero_states() {
    int i = blockIdx.x * blockDim.x + threadIdx.x;
    if (i < BB * HH) {
        g_h[i] = 0.f; g_c[i] = 0.f; g_d[i] = 0.f; g_cc[i] = 0.f;
    }
}

// ---------------- weight prep: transposes + combined biases ----------------
__global__ void prep(const float* __restrict__ encWhh, const float* __restrict__ decWhh,
                     const float* __restrict__ encWih, const float* __restrict__ decW1,
                     const float* __restrict__ ebih, const float* __restrict__ ebhh,
                     const float* __restrict__ dbih, const float* __restrict__ dbhh) {
    int idx = blockIdx.x * blockDim.x + threadIdx.x;
    if (idx < 65536) {                       // encWhhT[k*512+g] = encWhh[g*128+k]
        int g = idx & 511, k = idx >> 9;
        g_encWhhT[idx] = encWhh[g * 128 + k];
    } else if (idx < 131072) {
        int l = idx - 65536; int g = l & 511, k = l >> 9;
        g_decWhhT[l] = decWhh[g * 128 + k];
    } else if (idx < 196608) {
        int l = idx - 131072; int g = l & 511, m = l >> 9;
        g_encWihT[l] = encWih[g * 128 + m];
    } else if (idx < 229376) {               // W1dcT[k*128+h] = decW1[h*384+k], k<256
        int l = idx - 196608; int h = l & 127, k = l >> 7;
        g_W1dcT[l] = decW1[h * 384 + k];
    } else if (idx < 245760) {               // W1xT[k*128+h] = decW1[h*384+256+k]
        int l = idx - 229376; int h = l & 127, k = l >> 7;
        g_W1xT[l] = decW1[h * 384 + 256 + k];
    } else if (idx < 246272) {
        int g = idx - 245760;
        g_encBias[g] = ebih[g] + ebhh[g];
    } else if (idx < 246784) {
        int g = idx - 246272;
        g_decBias[g] = dbih[g] + dbhh[g];
    }
}

// ---------------- alpha: softmax_m( sum_t X[b,t,m]*Wa[2H+t] ) ----------------
__global__ void calc_alpha(const float* __restrict__ X, const float* __restrict__ Wa) {
    __shared__ float wa[TT];
    __shared__ float buf[MM];
    int b = blockIdx.x, m = threadIdx.x;
    if (m < TT) wa[m] = Wa[2 * HH + m];
    __syncthreads();
    const float* xb = X + b * TT * MM + m;
    float a0 = 0.f, a1 = 0.f, a2 = 0.f, a3 = 0.f;
#pragma unroll
    for (int tt = 0; tt < TT / 4; tt++) {
        a0 += xb[(tt * 4 + 0) * MM] * wa[tt * 4 + 0];
        a1 += xb[(tt * 4 + 1) * MM] * wa[tt * 4 + 1];
        a2 += xb[(tt * 4 + 2) * MM] * wa[tt * 4 + 2];
        a3 += xb[(tt * 4 + 3) * MM] * wa[tt * 4 + 3];
    }
    float s = (a0 + a1) + (a2 + a3);
    buf[m] = s; __syncthreads();
    for (int st = 64; st > 0; st >>= 1) {
        if (m < st) buf[m] = fmaxf(buf[m], buf[m + st]);
        __syncthreads();
    }
    float mx = buf[0]; __syncthreads();
    float e = __expf(s - mx);
    buf[m] = e; __syncthreads();
    for (int st = 64; st > 0; st >>= 1) {
        if (m < st) buf[m] += buf[m + st];
        __syncthreads();
    }
    g_alpha[b * MM + m] = e / buf[0];
}

// ---------------- generic GEMM: C[n,c] = sum_k A'[n,k]*Wt[k,c] + bias[c] ----------------
// A' = A (optionally scaled by alpha[(n/100)*128 + k]). Tile 64x128, K=128 in 4x32 chunks.
__global__ __launch_bounds__(256) void gemm64x128(
    const float* __restrict__ A, const float* __restrict__ alphaP,
    const float* __restrict__ Wt, const float* __restrict__ bias,
    float* __restrict__ C, int ncols)
{
    __shared__ float As[64][33];
    __shared__ float Ws[32][128];
    int n0 = blockIdx.x * 64;
    int c0 = blockIdx.y * 128;
    int tid = threadIdx.x;
    int tx = tid & 15, ty = tid >> 4;
    float acc[4][8];
#pragma unroll
    for (int r = 0; r < 4; r++)
#pragma unroll
        for (int i = 0; i < 8; i++) acc[r][i] = 0.f;

    // hoisted row indices for A loads
    int nrow[8], arow[8];
#pragma unroll
    for (int i = 0; i < 8; i++) {
        int idx = tid + i * 256;
        int r = idx >> 5;
        nrow[i] = n0 + r;
        arow[i] = (nrow[i] / TT) * MM;
    }

    for (int kt = 0; kt < 4; kt++) {
        int k0 = kt * 32;
#pragma unroll
        for (int i = 0; i < 8; i++) {
            int idx = tid + i * 256;
            int r = idx >> 5, k = idx & 31;
            float a = A[nrow[i] * MM + k0 + k];
            if (alphaP) a *= alphaP[arow[i] + k0 + k];
            As[r][k] = a;
        }
#pragma unroll
        for (int i = 0; i < 16; i++) {
            int idx = tid + i * 256;
            int k = idx >> 7, c = idx & 127;
            Ws[k][c] = Wt[(k0 + k) * ncols + c0 + c];
        }
        __syncthreads();
#pragma unroll
        for (int kk = 0; kk < 32; kk++) {
            float av[4];
#pragma unroll
            for (int r = 0; r < 4; r++) av[r] = As[ty * 4 + r][kk];
            float4 w0 = *reinterpret_cast<const float4*>(&Ws[kk][tx * 8]);
            float4 w1 = *reinterpret_cast<const float4*>(&Ws[kk][tx * 8 + 4]);
            float wv[8] = {w0.x, w0.y, w0.z, w0.w, w1.x, w1.y, w1.z, w1.w};
#pragma unroll
            for (int r = 0; r < 4; r++)
#pragma unroll
                for (int i = 0; i < 8; i++) acc[r][i] += av[r] * wv[i];
        }
        __syncthreads();
    }
#pragma unroll
    for (int r = 0; r < 4; r++) {
        int n = n0 + ty * 4 + r;
#pragma unroll
        for (int i = 0; i < 8; i++) {
            int c = c0 + tx * 8 + i;
            C[n * ncols + c] = acc[r][i] + bias[c];
        }
    }
}

// ---------------- encoder LSTM step: gates = G1[:,t,:] + h@WhhT; update h,c ----------------
__global__ __launch_bounds__(512) void enc_step(int t) {
    __shared__ float hs[8][HH];
    __shared__ float gs[8][GG];
    int b0 = blockIdx.x * 8;
    int tid = threadIdx.x;
#pragma unroll
    for (int i = 0; i < 2; i++) {
        int idx = tid + i * 512;
        int r = idx >> 7, k = idx & 127;
        hs[r][k] = g_h[(b0 + r) * HH + k];
    }
    __syncthreads();
    int g = tid;
    float acc[8] = {0.f, 0.f, 0.f, 0.f, 0.f, 0.f, 0.f, 0.f};
#pragma unroll 8
    for (int k = 0; k < HH; k++) {
        float w = g_encWhhT[k * GG + g];
#pragma unroll
        for (int r = 0; r < 8; r++) acc[r] += hs[r][k] * w;
    }
#pragma unroll
    for (int r = 0; r < 8; r++)
        gs[r][g] = acc[r] + g_G1[((b0 + r) * TT + t) * GG + g];
    __syncthreads();
#pragma unroll
    for (int i = 0; i < 2; i++) {
        int idx = tid + i * 512;
        int r = idx >> 7, j = idx & 127;
        int row = b0 + r;
        float iv = gs[r][j], fv = gs[r][j + 128], gv = gs[r][j + 256], ov = gs[r][j + 384];
        float co = g_c[row * HH + j];
        float cn = sigm(fv) * co + sigm(iv) * tanh_s(gv);
        float hn = sigm(ov) * tanh_s(cn);
        g_c[row * HH + j] = cn;
        g_h[row * HH + j] = hn;
        g_Xenc[(row * TT + t) * HH + j] = hn;
    }
}

// ---------------- decoder u projection: u = d@W1d^T + c@W1c^T (no bias; b1 lives in preX) ----
__global__ __launch_bounds__(256) void dec_u() {
    __shared__ float ds[8][256];
    __shared__ float red[8][128];
    int b0 = blockIdx.x * 8;
    int tid = threadIdx.x;
#pragma unroll
    for (int i = 0; i < 8; i++) {
        int idx = tid + i * 256;
        int r = idx >> 8, p = idx & 255;
        ds[r][p] = (p < 128) ? g_d[(b0 + r) * PP + p] : g_cc[(b0 + r) * PP + (p - 128)];
    }
    __syncthreads();
    int tx = tid & 127, ty = tid >> 7;  // ty: which K-half
    float acc[8] = {0.f, 0.f, 0.f, 0.f, 0.f, 0.f, 0.f, 0.f};
#pragma unroll 8
    for (int k = 0; k < 128; k++) {
        int kk = ty * 128 + k;
        float w = g_W1dcT[kk * HH + tx];
#pragma unroll
        for (int r = 0; r < 8; r++) acc[r] += ds[r][kk] * w;
    }
    if (ty == 1) {
#pragma unroll
        for (int r = 0; r < 8; r++) red[r][tx] = acc[r];
    }
    __syncthreads();
    if (ty == 0) {
#pragma unroll
        for (int r = 0; r < 8; r++)
            g_u[(b0 + r) * HH + tx] = acc[r] + red[r][tx];
    }
}

// ---------------- decoder attention: score->softmax->ctx->y ----------------
__global__ __launch_bounds__(128) void dec_attn(const float* __restrict__ decW2,
                                                const float* __restrict__ fcW,
                                                const float* __restrict__ fcB) {
    __shared__ float u_s[HH], w2_s[HH], fw_s[HH], sc[128], buf[128];
    int b = blockIdx.x;
    int j = threadIdx.x;
    u_s[j] = g_u[b * HH + j];
    w2_s[j] = decW2[j];
    fw_s[j] = fcW[j];
    __syncthreads();
    int lane = j & 31, w = j >> 5;
    // pass 1: scores (warp per t)
    for (int it = 0; it < 25; it++) {
        int t = it * 4 + w;
        const float* px = &g_preX[(b * TT + t) * HH];
        float s = 0.f;
#pragma unroll
        for (int q = 0; q < 4; q++) {
            int h = lane + q * 32;
            s += tanh_fast(px[h] + u_s[h]) * w2_s[h];
        }
#pragma unroll
        for (int off = 16; off > 0; off >>= 1)
            s += __shfl_down_sync(0xffffffffu, s, off);
        if (lane == 0) sc[t] = s;
    }
    __syncthreads();
    // softmax over t=0..99
    float v = (j < TT) ? sc[j] : -1e30f;
    buf[j] = v; __syncthreads();
    for (int st = 64; st > 0; st >>= 1) {
        if (j < st) buf[j] = fmaxf(buf[j], buf[j + st]);
        __syncthreads();
    }
    float mx = buf[0]; __syncthreads();
    float e = (j < TT) ? __expf(v - mx) : 0.f;
    buf[j] = e; __syncthreads();
    for (int st = 64; st > 0; st >>= 1) {
        if (j < st) buf[j] += buf[j + st];
        __syncthreads();
    }
    float inv = 1.0f / buf[0];
    __syncthreads();
    if (j < TT) sc[j] = e * inv;
    __syncthreads();
    // pass 2: ctx[j] = sum_t beta[t]*X_enc[b,t,j]
    const float* xb = &g_Xenc[b * TT * HH + j];
    float a0 = 0.f, a1 = 0.f, a2 = 0.f, a3 = 0.f;
#pragma unroll
    for (int tt = 0; tt < TT / 4; tt++) {
        a0 += sc[tt * 4 + 0] * xb[(tt * 4 + 0) * HH];
        a1 += sc[tt * 4 + 1] * xb[(tt * 4 + 1) * HH];
        a2 += sc[tt * 4 + 2] * xb[(tt * 4 + 2) * HH];
        a3 += sc[tt * 4 + 3] * xb[(tt * 4 + 3) * HH];
    }
    float acc = (a0 + a1) + (a2 + a3);
    g_ctx[b * HH + j] = acc;
    // y = ctx . fcW + fcB
    buf[j] = acc * fw_s[j];
    __syncthreads();
    for (int st = 64; st > 0; st >>= 1) {
        if (j < st) buf[j] += buf[j + st];
        __syncthreads();
    }
    if (j == 0) g_y[b] = buf[0] + fcB[0];
}

// ---------------- decoder LSTM step ----------------
__global__ __launch_bounds__(512) void dec_step(const float* __restrict__ decWih) {
    __shared__ float hs[8][PP];
    __shared__ float ys[8];
    __shared__ float gs[8][GG];
    int b0 = blockIdx.x * 8;
    int tid = threadIdx.x;
#pragma unroll
    for (int i = 0; i < 2; i++) {
        int idx = tid + i * 512;
        int r = idx >> 7, k = idx & 127;
        hs[r][k] = g_d[(b0 + r) * PP + k];
    }
    if (tid < 8) ys[tid] = g_y[b0 + tid];
    __syncthreads();
    int g = tid;
    float acc[8] = {0.f, 0.f, 0.f, 0.f, 0.f, 0.f, 0.f, 0.f};
#pragma unroll 8
    for (int k = 0; k < PP; k++) {
        float w = g_decWhhT[k * GG + g];
#pragma unroll
        for (int r = 0; r < 8; r++) acc[r] += hs[r][k] * w;
    }
    float wih = decWih[g];
    float bia = g_decBias[g];
#pragma unroll
    for (int r = 0; r < 8; r++)
        gs[r][g] = acc[r] + ys[r] * wih + bia;
    __syncthreads();
#pragma unroll
    for (int i = 0; i < 2; i++) {
        int idx = tid + i * 512;
        int r = idx >> 7, j = idx & 127;
        int row = b0 + r;
        float iv = gs[r][j], fv = gs[r][j + 128], gv = gs[r][j + 256], ov = gs[r][j + 384];
        float co = g_cc[row * PP + j];
        float cn = sigm(fv) * co + sigm(iv) * tanh_s(gv);
        float hn = sigm(ov) * tanh_s(cn);
        g_cc[row * PP + j] = cn;
        g_d[row * PP + j] = hn;
    }
}

// ---------------- final: out = [d, ctx] @ fcfW^T + fcfb ----------------
__global__ __launch_bounds__(256) void final_fc(const float* __restrict__ fcfW,
                                                const float* __restrict__ fcfB,
                                                float* __restrict__ out) {
    __shared__ float wf[CC * 256];
    int tid = threadIdx.x;
#pragma unroll
    for (int i = 0; i < 32; i++) wf[tid + i * 256] = fcfW[tid + i * 256];
    __syncthreads();
    int cl = tid >> 3;
    int bi = tid & 7;
    int b = blockIdx.x * 8 + bi;
    const float* dd = &g_d[b * PP];
    const float* cx = &g_ctx[b * HH];
    float acc = fcfB[cl];
#pragma unroll 8
    for (int k = 0; k < 128; k++) acc += dd[k] * wf[cl * 256 + k];
#pragma unroll 8
    for (int k = 0; k < 128; k++) acc += cx[k] * wf[cl * 256 + 128 + k];
    out[b * CC + cl] = acc;
}

// ---------------- host launcher ----------------
extern "C" void kernel_launch(void* const* d_in, const int* in_sizes, int n_in,
                              void* d_out, int out_size) {
    (void)in_sizes; (void)n_in; (void)out_size;
    const float* X       = (const float*)d_in[0];
    const float* encWih  = (const float*)d_in[1];
    const float* encWhh  = (const float*)d_in[2];
    const float* encBih  = (const float*)d_in[3];
    const float* encBhh  = (const float*)d_in[4];
    const float* encAttW = (const float*)d_in[5];
    // d_in[6] enc_attn_b: constant shift, drops out of softmax
    const float* decW1   = (const float*)d_in[7];
    const float* decB1   = (const float*)d_in[8];
    const float* decW2   = (const float*)d_in[9];
    // d_in[10] dec_b2: drops out of softmax
    const float* decWih  = (const float*)d_in[11];
    const float* decWhh  = (const float*)d_in[12];
    const float* decBih  = (const float*)d_in[13];
    const float* decBhh  = (const float*)d_in[14];
    const float* fcW     = (const float*)d_in[15];
    const float* fcB     = (const float*)d_in[16];
    const float* fcfW    = (const float*)d_in[17];
    const float* fcfB    = (const float*)d_in[18];
    float* out = (float*)d_out;

    void *pG1, *pXenc, *pPreX, *pAlpha, *pEncWihT, *pW1xT, *pEncBias;
    cudaGetSymbolAddress(&pG1, g_G1);
    cudaGetSymbolAddress(&pXenc, g_Xenc);
    cudaGetSymbolAddress(&pPreX, g_preX);
    cudaGetSymbolAddress(&pAlpha, g_alpha);
    cudaGetSymbolAddress(&pEncWihT, g_encWihT);
    cudaGetSymbolAddress(&pW1xT, g_W1xT);
    cudaGetSymbolAddress(&pEncBias, g_encBias);

    zero_states<<<512, 256>>>();
    prep<<<964, 256>>>(encWhh, decWhh, encWih, decW1, encBih, encBhh, decBih, decBhh);
    calc_alpha<<<BB, 128>>>(X, encAttW);

    // G1 = (alpha * X) @ encWih^T + (bih + bhh)  : [102400,128]@[128,512]
    gemm64x128<<<dim3(BB * TT / 64, 4), 256>>>(
        X, (const float*)pAlpha, (const float*)pEncWihT,
        (const float*)pEncBias, (float*)pG1, GG);

    for (int t = 0; t < TT; t++)
        enc_step<<<BB / 8, 512>>>(t);

    // preX = X_enc @ W1x^T + b1 : [102400,128]@[128,128]
    gemm64x128<<<dim3(BB * TT / 64, 1), 256>>>(
        (const float*)pXenc, nullptr, (const float*)pW1xT,
        decB1, (float*)pPreX, HH);

    for (int t = 0; t < TT; t++) {
        dec_u<<<BB / 8, 256>>>();
        dec_attn<<<BB, 128>>>(decW2, fcW, fcB);
        dec_step<<<BB / 8, 512>>>(decWih);
    }

    final_fc<<<BB / 8, 256>>>(fcfW, fcfB, out);
}

// round 5
// speedup vs baseline: 1.9466x; 1.9466x over previous
#include <cuda_runtime.h>
#include <cuda_bf16.h>
#include <cstdint>

// Problem dims
#define BB 1024
#define TTT 100
#define MM 128
#define HH 128
#define PP 128
#define CC 32
#define GG 512   // 4H

// ---------------- device scratch (static, no allocation) ----------------
__device__ float g_alpha[BB * MM];                      // 512 KB
__device__ float g_Xenc[(size_t)BB * TTT * HH];         // 52.4 MB (fp32, feeds ctx)
__device__ __nv_bfloat16 g_preX16[(size_t)BB * TTT * HH]; // 26.2 MB (bf16, score path only)
__device__ float g_encWcT[256 * GG];                    // [k][g]: k<128 Wih, k>=128 Whh
__device__ float g_decWhhT[128 * GG];                   // [k][g]
__device__ float g_W1dcT[256 * HH];                     // [k][h]
__device__ float g_W1xT[128 * HH];                      // [k][h]
__device__ float g_encBias[GG];
__device__ float g_decBias[GG];

// ---------------- helpers ----------------
__device__ __forceinline__ float sigm(float x) {
    return 1.0f / (1.0f + __expf(-x));
}
__device__ __forceinline__ float tanh_s(float x) {   // accurate tanh (exp-based)
    float a = fabsf(x);
    float e = __expf(-2.0f * a);
    float r = (1.0f - e) / (1.0f + e);
    return copysignf(r, x);
}
__device__ __forceinline__ float tanh_fast(float x) { // MUFU.TANH
    float y;
    asm("tanh.approx.f32 %0, %1;" : "=f"(y) : "f"(x));
    return y;
}

// ---------------- weight prep: transposes + combined biases ----------------
__global__ void prep(const float* __restrict__ encWih, const float* __restrict__ encWhh,
                     const float* __restrict__ decWhh, const float* __restrict__ decW1,
                     const float* __restrict__ ebih, const float* __restrict__ ebhh,
                     const float* __restrict__ dbih, const float* __restrict__ dbhh) {
    int idx = blockIdx.x * blockDim.x + threadIdx.x;
    if (idx < 131072) {                       // encWcT[k*512+g]
        int k = idx >> 9, gg = idx & 511;
        g_encWcT[idx] = (k < 128) ? encWih[gg * 128 + k] : encWhh[gg * 128 + (k - 128)];
    } else if (idx < 196608) {                // decWhhT[k*512+g]
        int l = idx - 131072; int k = l >> 9, gg = l & 511;
        g_decWhhT[l] = decWhh[gg * 128 + k];
    } else if (idx < 229376) {                // W1dcT[k*128+h] = decW1[h*384+k], k<256
        int l = idx - 196608; int hh = l & 127, k = l >> 7;
        g_W1dcT[l] = decW1[hh * 384 + k];
    } else if (idx < 245760) {                // W1xT[k*128+h] = decW1[h*384+256+k]
        int l = idx - 229376; int hh = l & 127, k = l >> 7;
        g_W1xT[l] = decW1[hh * 384 + 256 + k];
    } else if (idx < 246272) {
        int gg = idx - 245760; g_encBias[gg] = ebih[gg] + ebhh[gg];
    } else if (idx < 246784) {
        int gg = idx - 246272; g_decBias[gg] = dbih[gg] + dbhh[gg];
    }
}

// ---------------- alpha: softmax_m( sum_t X[b,t,m]*Wa[2H+t] ) ----------------
__global__ void calc_alpha(const float* __restrict__ X, const float* __restrict__ Wa) {
    __shared__ float wa[TTT];
    __shared__ float buf[MM];
    int b = blockIdx.x, m = threadIdx.x;
    if (m < TTT) wa[m] = Wa[2 * HH + m];
    __syncthreads();
    const float* xb = X + (size_t)b * TTT * MM + m;
    float a0 = 0.f, a1 = 0.f, a2 = 0.f, a3 = 0.f;
#pragma unroll
    for (int tt = 0; tt < TTT / 4; tt++) {
        a0 += xb[(tt * 4 + 0) * MM] * wa[tt * 4 + 0];
        a1 += xb[(tt * 4 + 1) * MM] * wa[tt * 4 + 1];
        a2 += xb[(tt * 4 + 2) * MM] * wa[tt * 4 + 2];
        a3 += xb[(tt * 4 + 3) * MM] * wa[tt * 4 + 3];
    }
    float s = (a0 + a1) + (a2 + a3);
    buf[m] = s; __syncthreads();
    for (int st = 64; st > 0; st >>= 1) {
        if (m < st) buf[m] = fmaxf(buf[m], buf[m + st]);
        __syncthreads();
    }
    float mx = buf[0]; __syncthreads();
    float e = __expf(s - mx);
    buf[m] = e; __syncthreads();
    for (int st = 64; st > 0; st >>= 1) {
        if (m < st) buf[m] += buf[m + st];
        __syncthreads();
    }
    g_alpha[b * MM + m] = e / buf[0];
}

// ---------------- fused encoder: whole 100-step recurrence in one kernel ----------------
// block = 8 batch rows, 512 threads; gates = [x_tilde ; h] @ WcT + bias
__global__ __launch_bounds__(512, 1) void enc_fused(const float* __restrict__ X) {
    __shared__ float xhT[256][12];   // transposed [k][r] (pad 12 for alignment)
    __shared__ float gsb[8][512];
    __shared__ float cs[8][128];
    __shared__ float al[8][128];
    const int b0 = blockIdx.x * 8;
    const int tid = threadIdx.x;
    const int g = tid;
    const int jr = tid & 127, r0 = tid >> 7;
#pragma unroll
    for (int p = 0; p < 2; p++) {
        int r = r0 + p * 4;
        al[r][jr] = g_alpha[(b0 + r) * MM + jr];
        cs[r][jr] = 0.f;
        xhT[128 + jr][r] = 0.f;
    }
    const float bia = g_encBias[g];
    __syncthreads();
    for (int t = 0; t < TTT; t++) {
        // stage x_tilde (transposed)
#pragma unroll
        for (int p = 0; p < 2; p++) {
            int r = r0 + p * 4;
            xhT[jr][r] = X[((size_t)(b0 + r) * TTT + t) * MM + jr] * al[r][jr];
        }
        __syncthreads();
        float acc[8];
#pragma unroll
        for (int r = 0; r < 8; r++) acc[r] = 0.f;
#pragma unroll 8
        for (int k = 0; k < 256; k++) {
            float w = g_encWcT[k * GG + g];
            float4 a0 = *reinterpret_cast<const float4*>(&xhT[k][0]);
            float4 a1 = *reinterpret_cast<const float4*>(&xhT[k][4]);
            acc[0] += a0.x * w; acc[1] += a0.y * w; acc[2] += a0.z * w; acc[3] += a0.w * w;
            acc[4] += a1.x * w; acc[5] += a1.y * w; acc[6] += a1.z * w; acc[7] += a1.w * w;
        }
#pragma unroll
        for (int r = 0; r < 8; r++) gsb[r][g] = acc[r] + bia;
        __syncthreads();
#pragma unroll
        for (int p = 0; p < 2; p++) {
            int r = r0 + p * 4;
            float iv = gsb[r][jr], fv = gsb[r][jr + 128];
            float gv = gsb[r][jr + 256], ov = gsb[r][jr + 384];
            float cn = sigm(fv) * cs[r][jr] + sigm(iv) * tanh_s(gv);
            float hn = sigm(ov) * tanh_s(cn);
            cs[r][jr] = cn;
            xhT[128 + jr][r] = hn;
            g_Xenc[((size_t)(b0 + r) * TTT + t) * HH + jr] = hn;
        }
        __syncthreads();
    }
}

// ---------------- preX = Xenc @ W1x^T + b1 -> bf16 ----------------
__global__ __launch_bounds__(256) void gemm_preX(const float* __restrict__ b1) {
    __shared__ float As[64][33];
    __shared__ float Ws[32][128];
    int n0 = blockIdx.x * 64;
    int tid = threadIdx.x;
    int tx = tid & 15, ty = tid >> 4;
    float acc[4][8];
#pragma unroll
    for (int r = 0; r < 4; r++)
#pragma unroll
        for (int i = 0; i < 8; i++) acc[r][i] = 0.f;

    for (int kt = 0; kt < 4; kt++) {
        int k0 = kt * 32;
#pragma unroll
        for (int i = 0; i < 8; i++) {
            int idx = tid + i * 256;
            int r = idx >> 5, k = idx & 31;
            As[r][k] = g_Xenc[(size_t)(n0 + r) * HH + k0 + k];
        }
#pragma unroll
        for (int i = 0; i < 16; i++) {
            int idx = tid + i * 256;
            int k = idx >> 7, c = idx & 127;
            Ws[k][c] = g_W1xT[(k0 + k) * HH + c];
        }
        __syncthreads();
#pragma unroll
        for (int kk = 0; kk < 32; kk++) {
            float av[4];
#pragma unroll
            for (int r = 0; r < 4; r++) av[r] = As[ty * 4 + r][kk];
            float4 w0 = *reinterpret_cast<const float4*>(&Ws[kk][tx * 8]);
            float4 w1 = *reinterpret_cast<const float4*>(&Ws[kk][tx * 8 + 4]);
            float wv[8] = {w0.x, w0.y, w0.z, w0.w, w1.x, w1.y, w1.z, w1.w};
#pragma unroll
            for (int r = 0; r < 4; r++)
#pragma unroll
                for (int i = 0; i < 8; i++) acc[r][i] += av[r] * wv[i];
        }
        __syncthreads();
    }
#pragma unroll
    for (int r = 0; r < 4; r++) {
        int n = n0 + ty * 4 + r;
#pragma unroll
        for (int i = 0; i < 8; i++) {
            int c = tx * 8 + i;
            g_preX16[(size_t)n * HH + c] = __float2bfloat16(acc[r][i] + b1[c]);
        }
    }
}

// ---------------- fused decoder: whole 100-step loop + final FC in one kernel ---------
// dynamic smem layout (floats):
//   WhhS  [64][512]   32768   (k<64 half of decWhhT; reused as fcfW[32][257] at end)
//   dcatT [256][12]    3072   (transposed [d;cc])
//   gsb               4096
//   u_s   [8][128]    1024
//   ctx_s [8][128]    1024
//   scb   [8][104]     832
//   y_s                  8
//   w2_s               128
//   fw_s               128
#define DEC_SMEM_FLOATS (32768 + 3072 + 4096 + 1024 + 1024 + 832 + 8 + 128 + 128)

__global__ __launch_bounds__(512, 1) void dec_fused(
    const float* __restrict__ decWih, const float* __restrict__ decW2,
    const float* __restrict__ fcW, const float* __restrict__ fcB,
    const float* __restrict__ fcfW, const float* __restrict__ fcfB,
    float* __restrict__ out)
{
    extern __shared__ float sm[];
    float* WhhS  = sm;
    float* dcatT = sm + 32768;
    float* gsb   = dcatT + 3072;
    float* u_s   = gsb + 4096;
    float* ctx_s = u_s + 1024;
    float* scb   = ctx_s + 1024;
    float* y_s   = scb + 832;
    float* w2_s  = y_s + 8;
    float* fw_s  = w2_s + 128;

    const int b0 = blockIdx.x * 8;
    const int tid = threadIdx.x;
    const int g = tid;
    const int lane = tid & 31, wp = tid >> 5;
    const int h = tid & 127, q = tid >> 7;      // phase A mapping
    const int r8 = tid >> 6;                    // phase D: 8 rows
    const int j2 = (tid & 63) * 2;

    // preload Whh first half into smem (linear copy, same layout)
#pragma unroll
    for (int i = 0; i < 64; i++) WhhS[tid + i * 512] = g_decWhhT[tid + i * 512];
    for (int i = tid; i < 3072; i += 512) dcatT[i] = 0.f;
    if (tid < 128) { w2_s[tid] = decW2[tid]; fw_s[tid] = fcW[tid]; }
    // W1dc slice in registers: thread (q,h) holds k = q*64 .. q*64+63
    float w1r[64];
#pragma unroll
    for (int kk = 0; kk < 64; kk++)
        w1r[kk] = g_W1dcT[(q * 64 + kk) * HH + h];
    const float wih_g = decWih[g];
    const float bia_g = g_decBias[g];
    const float fcb = fcB[0];
    __syncthreads();
    const float4 w2v = *reinterpret_cast<const float4*>(&w2_s[lane * 4]);
    const float4 fwv = *reinterpret_cast<const float4*>(&fw_s[lane * 4]);

    for (int t = 0; t < TTT; t++) {
        // ---- A: u = [d;cc] @ W1dc^T  (partials over k-quarters)
        float acc[8];
#pragma unroll
        for (int r = 0; r < 8; r++) acc[r] = 0.f;
#pragma unroll
        for (int kk = 0; kk < 64; kk++) {
            int k = q * 64 + kk;
            float4 d0 = *reinterpret_cast<const float4*>(&dcatT[k * 12]);
            float4 d1 = *reinterpret_cast<const float4*>(&dcatT[k * 12 + 4]);
            float w = w1r[kk];
            acc[0] += d0.x * w; acc[1] += d0.y * w; acc[2] += d0.z * w; acc[3] += d0.w * w;
            acc[4] += d1.x * w; acc[5] += d1.y * w; acc[6] += d1.z * w; acc[7] += d1.w * w;
        }
#pragma unroll
        for (int r = 0; r < 8; r++) gsb[(q * 8 + r) * 128 + h] = acc[r];
        __syncthreads();
        {
            int jr = tid & 127, r0 = tid >> 7;
#pragma unroll
            for (int p = 0; p < 2; p++) {
                int r = r0 + p * 4;
                u_s[r * 128 + jr] = gsb[r * 128 + jr] + gsb[(8 + r) * 128 + jr]
                                  + gsb[(16 + r) * 128 + jr] + gsb[(24 + r) * 128 + jr];
            }
        }
        __syncthreads();
        // ---- B: scores s[r][t2] = sum_h tanh(preX+u) * w2   (warp per item)
        for (int n = 0; n < 50; n++) {
            int i = n * 16 + wp;             // 0..799
            int r = i / 100;
            int t2 = i - r * 100;
            const __nv_bfloat16* px = g_preX16 + (((size_t)(b0 + r) * TTT + t2) << 7);
            float4 uv = *reinterpret_cast<const float4*>(&u_s[r * 128 + lane * 4]);
            uint2 raw = *reinterpret_cast<const uint2*>(px + lane * 4);
            unsigned int rx = raw.x, ry = raw.y;
            __nv_bfloat162 p0 = *reinterpret_cast<__nv_bfloat162*>(&rx);
            __nv_bfloat162 p1 = *reinterpret_cast<__nv_bfloat162*>(&ry);
            float2 f0 = __bfloat1622float2(p0);
            float2 f1 = __bfloat1622float2(p1);
            float s = tanh_fast(f0.x + uv.x) * w2v.x + tanh_fast(f0.y + uv.y) * w2v.y
                    + tanh_fast(f1.x + uv.z) * w2v.z + tanh_fast(f1.y + uv.w) * w2v.w;
#pragma unroll
            for (int off = 16; off; off >>= 1) s += __shfl_xor_sync(0xffffffffu, s, off);
            if (lane == 0) scb[r * 104 + t2] = s;
        }
        __syncthreads();
        // ---- C: softmax over t (warp per row)
        if (wp < 8) {
            float v0 = scb[wp * 104 + lane];
            float v1 = scb[wp * 104 + lane + 32];
            float v2 = scb[wp * 104 + lane + 64];
            float v3 = (lane < 4) ? scb[wp * 104 + lane + 96] : -1e30f;
            float mx = fmaxf(fmaxf(v0, v1), fmaxf(v2, v3));
#pragma unroll
            for (int off = 16; off; off >>= 1)
                mx = fmaxf(mx, __shfl_xor_sync(0xffffffffu, mx, off));
            float e0 = __expf(v0 - mx), e1 = __expf(v1 - mx), e2 = __expf(v2 - mx);
            float e3 = (lane < 4) ? __expf(v3 - mx) : 0.f;
            float ss = e0 + e1 + e2 + e3;
#pragma unroll
            for (int off = 16; off; off >>= 1) ss += __shfl_xor_sync(0xffffffffu, ss, off);
            float inv = 1.f / ss;
            scb[wp * 104 + lane] = e0 * inv;
            scb[wp * 104 + lane + 32] = e1 * inv;
            scb[wp * 104 + lane + 64] = e2 * inv;
            if (lane < 4) scb[wp * 104 + lane + 96] = e3 * inv;
        }
        __syncthreads();
        // ---- D: ctx = beta @ Xenc   (thread = (row, 2 cols))
        {
            const float* xb = g_Xenc + ((size_t)(b0 + r8) * TTT) * HH + j2;
            float a0 = 0.f, a1 = 0.f;
#pragma unroll 4
            for (int t2 = 0; t2 < TTT; t2++) {
                float2 v = *reinterpret_cast<const float2*>(&xb[t2 * HH]);
                float be = scb[r8 * 104 + t2];
                a0 += be * v.x; a1 += be * v.y;
            }
            ctx_s[r8 * 128 + j2] = a0;
            ctx_s[r8 * 128 + j2 + 1] = a1;
        }
        __syncthreads();
        // ---- y = ctx . fcW + fcb  (warp per row)
        if (wp < 8) {
            float4 cv = *reinterpret_cast<const float4*>(&ctx_s[wp * 128 + lane * 4]);
            float s = cv.x * fwv.x + cv.y * fwv.y + cv.z * fwv.z + cv.w * fwv.w;
#pragma unroll
            for (int off = 16; off; off >>= 1) s += __shfl_xor_sync(0xffffffffu, s, off);
            if (lane == 0) y_s[wp] = s + fcb;
        }
        __syncthreads();
        // ---- E: LSTM gates = d @ Whh^T + y*wih + bias
        float accE[8];
#pragma unroll
        for (int r = 0; r < 8; r++) accE[r] = 0.f;
#pragma unroll 4
        for (int k = 0; k < 64; k++) {
            float w = WhhS[k * GG + g];
            float4 d0 = *reinterpret_cast<const float4*>(&dcatT[k * 12]);
            float4 d1 = *reinterpret_cast<const float4*>(&dcatT[k * 12 + 4]);
            accE[0] += d0.x * w; accE[1] += d0.y * w; accE[2] += d0.z * w; accE[3] += d0.w * w;
            accE[4] += d1.x * w; accE[5] += d1.y * w; accE[6] += d1.z * w; accE[7] += d1.w * w;
        }
#pragma unroll 4
        for (int k = 64; k < 128; k++) {
            float w = g_decWhhT[k * GG + g];
            float4 d0 = *reinterpret_cast<const float4*>(&dcatT[k * 12]);
            float4 d1 = *reinterpret_cast<const float4*>(&dcatT[k * 12 + 4]);
            accE[0] += d0.x * w; accE[1] += d0.y * w; accE[2] += d0.z * w; accE[3] += d0.w * w;
            accE[4] += d1.x * w; accE[5] += d1.y * w; accE[6] += d1.z * w; accE[7] += d1.w * w;
        }
#pragma unroll
        for (int r = 0; r < 8; r++)
            gsb[r * 512 + g] = accE[r] + y_s[r] * wih_g + bia_g;
        __syncthreads();
        // ---- F: state update (d, cc in transposed layout)
        {
            int jr = tid & 127, r0 = tid >> 7;
#pragma unroll
            for (int p = 0; p < 2; p++) {
                int r = r0 + p * 4;
                float iv = gsb[r * 512 + jr], fv = gsb[r * 512 + jr + 128];
                float gv = gsb[r * 512 + jr + 256], ov = gsb[r * 512 + jr + 384];
                float cold = dcatT[(128 + jr) * 12 + r];
                float cn = sigm(fv) * cold + sigm(iv) * tanh_s(gv);
                float hn = sigm(ov) * tanh_s(cn);
                dcatT[(128 + jr) * 12 + r] = cn;
                dcatT[jr * 12 + r] = hn;
            }
        }
        __syncthreads();
    }
    // ---- final FC: out = [d, ctx] @ fcfW^T + fcfb
    for (int i = tid; i < CC * 256; i += 512) {
        int cl = i >> 8, k = i & 255;
        WhhS[cl * 257 + k] = fcfW[i];       // padded 257 -> conflict-free reads
    }
    __syncthreads();
    if (tid < 256) {
        int cl = tid & 31, rl = tid >> 5;
        float a = fcfB[cl];
#pragma unroll 8
        for (int k = 0; k < 128; k++) a += dcatT[k * 12 + rl] * WhhS[cl * 257 + k];
#pragma unroll 8
        for (int k = 0; k < 128; k++) a += ctx_s[rl * 128 + k] * WhhS[cl * 257 + 128 + k];
        out[(b0 + rl) * CC + cl] = a;
    }
}

// ---------------- host launcher ----------------
extern "C" void kernel_launch(void* const* d_in, const int* in_sizes, int n_in,
                              void* d_out, int out_size) {
    (void)in_sizes; (void)n_in; (void)out_size;
    const float* X       = (const float*)d_in[0];
    const float* encWih  = (const float*)d_in[1];
    const float* encWhh  = (const float*)d_in[2];
    const float* encBih  = (const float*)d_in[3];
    const float* encBhh  = (const float*)d_in[4];
    const float* encAttW = (const float*)d_in[5];
    // d_in[6] enc_attn_b: constant shift, drops out of softmax
    const float* decW1   = (const float*)d_in[7];
    const float* decB1   = (const float*)d_in[8];
    const float* decW2   = (const float*)d_in[9];
    // d_in[10] dec_b2: drops out of softmax
    const float* decWih  = (const float*)d_in[11];
    const float* decWhh  = (const float*)d_in[12];
    const float* decBih  = (const float*)d_in[13];
    const float* decBhh  = (const float*)d_in[14];
    const float* fcW     = (const float*)d_in[15];
    const float* fcB     = (const float*)d_in[16];
    const float* fcfW    = (const float*)d_in[17];
    const float* fcfB    = (const float*)d_in[18];
    float* out = (float*)d_out;

    cudaFuncSetAttribute(dec_fused, cudaFuncAttributeMaxDynamicSharedMemorySize,
                         DEC_SMEM_FLOATS * 4);

    prep<<<964, 256>>>(encWih, encWhh, decWhh, decW1, encBih, encBhh, decBih, decBhh);
    calc_alpha<<<BB, 128>>>(X, encAttW);
    enc_fused<<<BB / 8, 512>>>(X);
    gemm_preX<<<BB * TTT / 64, 256>>>(decB1);
    dec_fused<<<BB / 8, 512, DEC_SMEM_FLOATS * 4>>>(decWih, decW2, fcW, fcB, fcfW, fcfB, out);
}

// round 6
// speedup vs baseline: 2.2091x; 1.1349x over previous
#include <cuda_runtime.h>
#include <cuda_bf16.h>
#include <cstdint>

// Problem dims
#define BB 1024
#define TTT 100
#define MM 128
#define HH 128
#define PP 128
#define CC 32
#define GG 512   // 4H

// ---------------- device scratch (static, no allocation) ----------------
__device__ float g_alpha[BB * MM];
__device__ float g_Xenc[(size_t)BB * TTT * HH];           // 52.4 MB fp32 (ctx path)
__device__ __nv_bfloat16 g_preX16[(size_t)BB * TTT * HH]; // 26.2 MB bf16 (score path)
__device__ float g_encWcT[256 * GG];                      // [k][g]: k<128 Wih, k>=128 Whh
__device__ float g_decWhhT[128 * GG];                     // [k][g]
__device__ float g_W1dcT[256 * HH];                       // [k][h]
__device__ float g_W1xT[128 * HH];                        // [k][h]
__device__ float g_encBias[GG];
__device__ float g_decBias[GG];

// ---------------- helpers ----------------
typedef unsigned long long ull;

__device__ __forceinline__ ull pack2(float x, float y) {
    ull r;
    asm("mov.b64 %0, {%1, %2};" : "=l"(r)
        : "r"(__float_as_uint(x)), "r"(__float_as_uint(y)));
    return r;
}
__device__ __forceinline__ float2 unpack2(ull v) {
    unsigned int lo, hi;
    asm("mov.b64 {%0, %1}, %2;" : "=r"(lo), "=r"(hi) : "l"(v));
    return make_float2(__uint_as_float(lo), __uint_as_float(hi));
}
__device__ __forceinline__ ull ffma2(ull a, ull b, ull c) {
    ull d;
    asm("fma.rn.f32x2 %0, %1, %2, %3;" : "=l"(d) : "l"(a), "l"(b), "l"(c));
    return d;
}
__device__ __forceinline__ float sigm(float x) {
    return 1.0f / (1.0f + __expf(-x));
}
__device__ __forceinline__ float tanh_s(float x) {   // accurate tanh (exp-based)
    float a = fabsf(x);
    float e = __expf(-2.0f * a);
    float r = (1.0f - e) / (1.0f + e);
    return copysignf(r, x);
}
__device__ __forceinline__ float tanh_fast(float x) { // MUFU.TANH
    float y;
    asm("tanh.approx.f32 %0, %1;" : "=f"(y) : "f"(x));
    return y;
}

// ---------------- weight prep: transposes + combined biases ----------------
__global__ void prep(const float* __restrict__ encWih, const float* __restrict__ encWhh,
                     const float* __restrict__ decWhh, const float* __restrict__ decW1,
                     const float* __restrict__ ebih, const float* __restrict__ ebhh,
                     const float* __restrict__ dbih, const float* __restrict__ dbhh) {
    int idx = blockIdx.x * blockDim.x + threadIdx.x;
    if (idx < 131072) {                       // encWcT[k*512+g]
        int k = idx >> 9, gg = idx & 511;
        g_encWcT[idx] = (k < 128) ? encWih[gg * 128 + k] : encWhh[gg * 128 + (k - 128)];
    } else if (idx < 196608) {                // decWhhT[k*512+g]
        int l = idx - 131072; int k = l >> 9, gg = l & 511;
        g_decWhhT[l] = decWhh[gg * 128 + k];
    } else if (idx < 229376) {                // W1dcT[k*128+h] = decW1[h*384+k], k<256
        int l = idx - 196608; int hh = l & 127, k = l >> 7;
        g_W1dcT[l] = decW1[hh * 384 + k];
    } else if (idx < 245760) {                // W1xT[k*128+h] = decW1[h*384+256+k]
        int l = idx - 229376; int hh = l & 127, k = l >> 7;
        g_W1xT[l] = decW1[hh * 384 + 256 + k];
    } else if (idx < 246272) {
        int gg = idx - 245760; g_encBias[gg] = ebih[gg] + ebhh[gg];
    } else if (idx < 246784) {
        int gg = idx - 246272; g_decBias[gg] = dbih[gg] + dbhh[gg];
    }
}

// ---------------- alpha: softmax_m( sum_t X[b,t,m]*Wa[2H+t] ) ----------------
__global__ void calc_alpha(const float* __restrict__ X, const float* __restrict__ Wa) {
    __shared__ float wa[TTT];
    __shared__ float buf[MM];
    int b = blockIdx.x, m = threadIdx.x;
    if (m < TTT) wa[m] = Wa[2 * HH + m];
    __syncthreads();
    const float* xb = X + (size_t)b * TTT * MM + m;
    float a0 = 0.f, a1 = 0.f, a2 = 0.f, a3 = 0.f;
#pragma unroll
    for (int tt = 0; tt < TTT / 4; tt++) {
        a0 += xb[(tt * 4 + 0) * MM] * wa[tt * 4 + 0];
        a1 += xb[(tt * 4 + 1) * MM] * wa[tt * 4 + 1];
        a2 += xb[(tt * 4 + 2) * MM] * wa[tt * 4 + 2];
        a3 += xb[(tt * 4 + 3) * MM] * wa[tt * 4 + 3];
    }
    float s = (a0 + a1) + (a2 + a3);
    buf[m] = s; __syncthreads();
    for (int st = 64; st > 0; st >>= 1) {
        if (m < st) buf[m] = fmaxf(buf[m], buf[m + st]);
        __syncthreads();
    }
    float mx = buf[0]; __syncthreads();
    float e = __expf(s - mx);
    buf[m] = e; __syncthreads();
    for (int st = 64; st > 0; st >>= 1) {
        if (m < st) buf[m] += buf[m + st];
        __syncthreads();
    }
    g_alpha[b * MM + m] = e / buf[0];
}

// ---------------- fused encoder: 100-step recurrence, 1024 thr, f32x2 ----------------
__global__ __launch_bounds__(1024, 1) void enc_fused(const float* __restrict__ X) {
    __shared__ float xhT[256][12];      // transposed [k][row]
    __shared__ float gsb[2][8][512];    // k-half partials
    const int b0 = blockIdx.x * 8;
    const int tid = threadIdx.x;
    const int g  = tid & 511;
    const int kh = tid >> 9;            // 0/1 : k half
    const int jr = tid & 127;
    const int r  = tid >> 7;            // 0..7 (used in elementwise phases)
    const float al = g_alpha[(b0 + r) * MM + jr];
    float bia4[4];
#pragma unroll
    for (int x = 0; x < 4; x++) bia4[x] = g_encBias[jr + 128 * x];
    float c_reg = 0.f;
    xhT[128 + jr][r] = 0.f;             // h0 = 0
    const float* wbase = g_encWcT + (size_t)kh * 128 * 512 + g;
    const size_t xrow = (size_t)(b0 + r) * TTT;
    float xv = X[xrow * MM + jr] * al;  // t=0

    for (int t = 0; t < TTT; t++) {
        xhT[jr][r] = xv;
        __syncthreads();
        // prefetch next step's x
        int tn = (t < TTT - 1) ? t + 1 : t;
        float xnext = X[(xrow + tn) * MM + jr];
        // gate GEMM: [8 rows] x [256 k] for this thread's (g, kh)
        ull a0 = 0, a1 = 0, a2 = 0, a3 = 0;
        const float* wp = wbase;
        const float (*xk)[12] = &xhT[kh * 128];
#pragma unroll 4
        for (int k = 0; k < 128; k++) {
            float w = wp[k * 512];
            ull ww = pack2(w, w);
            ulonglong2 p0 = *reinterpret_cast<const ulonglong2*>(&xk[k][0]);
            ulonglong2 p1 = *reinterpret_cast<const ulonglong2*>(&xk[k][4]);
            a0 = ffma2(p0.x, ww, a0);
            a1 = ffma2(p0.y, ww, a1);
            a2 = ffma2(p1.x, ww, a2);
            a3 = ffma2(p1.y, ww, a3);
        }
        float2 f;
        f = unpack2(a0); gsb[kh][0][g] = f.x; gsb[kh][1][g] = f.y;
        f = unpack2(a1); gsb[kh][2][g] = f.x; gsb[kh][3][g] = f.y;
        f = unpack2(a2); gsb[kh][4][g] = f.x; gsb[kh][5][g] = f.y;
        f = unpack2(a3); gsb[kh][6][g] = f.x; gsb[kh][7][g] = f.y;
        __syncthreads();
        // nonlinearity for (r, jr)
        float iv = gsb[0][r][jr      ] + gsb[1][r][jr      ] + bia4[0];
        float fv = gsb[0][r][jr + 128] + gsb[1][r][jr + 128] + bia4[1];
        float gv = gsb[0][r][jr + 256] + gsb[1][r][jr + 256] + bia4[2];
        float ov = gsb[0][r][jr + 384] + gsb[1][r][jr + 384] + bia4[3];
        float cn = sigm(fv) * c_reg + sigm(iv) * tanh_s(gv);
        float hn = sigm(ov) * tanh_s(cn);
        c_reg = cn;
        xhT[128 + jr][r] = hn;
        g_Xenc[(xrow + t) * HH + jr] = hn;
        xv = xnext * al;
    }
}

// ---------------- preX = Xenc @ W1x^T + b1 -> bf16 (f32x2 inner) ----------------
__global__ __launch_bounds__(256) void gemm_preX(const float* __restrict__ b1) {
    __shared__ float As[64][33];
    __shared__ float Ws[32][128];
    int n0 = blockIdx.x * 64;
    int tid = threadIdx.x;
    int tx = tid & 15, ty = tid >> 4;
    ull acc[4][4];
#pragma unroll
    for (int r = 0; r < 4; r++)
#pragma unroll
        for (int i = 0; i < 4; i++) acc[r][i] = 0;

    for (int kt = 0; kt < 4; kt++) {
        int k0 = kt * 32;
#pragma unroll
        for (int i = 0; i < 8; i++) {
            int idx = tid + i * 256;
            int r = idx >> 5, k = idx & 31;
            As[r][k] = g_Xenc[(size_t)(n0 + r) * HH + k0 + k];
        }
#pragma unroll
        for (int i = 0; i < 16; i++) {
            int idx = tid + i * 256;
            int k = idx >> 7, c = idx & 127;
            Ws[k][c] = g_W1xT[(k0 + k) * HH + c];
        }
        __syncthreads();
#pragma unroll
        for (int kk = 0; kk < 32; kk++) {
            ulonglong2 w0 = *reinterpret_cast<const ulonglong2*>(&Ws[kk][tx * 8]);
            ulonglong2 w1 = *reinterpret_cast<const ulonglong2*>(&Ws[kk][tx * 8 + 4]);
#pragma unroll
            for (int r = 0; r < 4; r++) {
                float av = As[ty * 4 + r][kk];
                ull avv = pack2(av, av);
                acc[r][0] = ffma2(avv, w0.x, acc[r][0]);
                acc[r][1] = ffma2(avv, w0.y, acc[r][1]);
                acc[r][2] = ffma2(avv, w1.x, acc[r][2]);
                acc[r][3] = ffma2(avv, w1.y, acc[r][3]);
            }
        }
        __syncthreads();
    }
#pragma unroll
    for (int r = 0; r < 4; r++) {
        int n = n0 + ty * 4 + r;
#pragma unroll
        for (int i = 0; i < 4; i++) {
            float2 f = unpack2(acc[r][i]);
            int c = tx * 8 + i * 2;
            g_preX16[(size_t)n * HH + c]     = __float2bfloat16(f.x + b1[c]);
            g_preX16[(size_t)n * HH + c + 1] = __float2bfloat16(f.y + b1[c + 1]);
        }
    }
}

// ---------------- fused decoder: 100 steps + final FC, 1024 thr, f32x2 ----------------
// dynamic smem floats:
//   W1dcS [256][128] 32768 (reused as fcfW[32][257] at end)
//   dcatT [256][12]   3072
//   gsb               8192
//   u_s               1024
//   ctx_s             1024
//   scb  [8][104]      832
//   y_s                  8
//   w2_s               128
//   fw_s               128
#define DEC_SMEM_FLOATS (32768 + 3072 + 8192 + 1024 + 1024 + 832 + 8 + 128 + 128)

__global__ __launch_bounds__(1024, 1) void dec_fused(
    const float* __restrict__ decWih, const float* __restrict__ decW2,
    const float* __restrict__ fcW, const float* __restrict__ fcB,
    const float* __restrict__ fcfW, const float* __restrict__ fcfB,
    float* __restrict__ out)
{
    extern __shared__ float sm[];
    float* W1dcS = sm;
    float* dcatT = sm + 32768;
    float* gsb   = dcatT + 3072;
    float* u_s   = gsb + 8192;
    float* ctx_s = u_s + 1024;
    float* scb   = ctx_s + 1024;
    float* y_s   = scb + 832;
    float* w2_s  = y_s + 8;
    float* fw_s  = w2_s + 128;

    const int b0 = blockIdx.x * 8;
    const int tid = threadIdx.x;
    const int lane = tid & 31, wp = tid >> 5;
    const int jr = tid & 127;
    const int r  = tid >> 7;        // 0..7 (also the A-phase k-slice index)
    const int g  = tid & 511;
    const int kh = tid >> 9;        // 0/1 for E phase

    for (int i = tid; i < 32768; i += 1024) W1dcS[i] = g_W1dcT[i];
    for (int i = tid; i < 3072; i += 1024) dcatT[i] = 0.f;
    if (tid < 128) { w2_s[tid] = decW2[tid]; fw_s[tid] = fcW[tid]; }
    float wih4[4], bia4[4];
#pragma unroll
    for (int x = 0; x < 4; x++) {
        wih4[x] = decWih[jr + 128 * x];
        bia4[x] = g_decBias[jr + 128 * x];
    }
    float c_reg = 0.f;
    const float fcb = fcB[0];
    __syncthreads();
    const float4 w2v = *reinterpret_cast<const float4*>(&w2_s[lane * 4]);
    const float4 fwv = *reinterpret_cast<const float4*>(&fw_s[lane * 4]);

    for (int t = 0; t < TTT; t++) {
        // ---- A: u = [d;cc] @ W1dc^T (k-slice r*32..r*32+31 per thread)
        {
            ull a0 = 0, a1 = 0, a2 = 0, a3 = 0;
            const float* wA = W1dcS + (r * 32) * 128 + jr;
            const float* dk = dcatT + (r * 32) * 12;
#pragma unroll 4
            for (int kk = 0; kk < 32; kk++) {
                float w = wA[kk * 128];
                ull ww = pack2(w, w);
                ulonglong2 p0 = *reinterpret_cast<const ulonglong2*>(dk + kk * 12);
                ulonglong2 p1 = *reinterpret_cast<const ulonglong2*>(dk + kk * 12 + 4);
                a0 = ffma2(p0.x, ww, a0);
                a1 = ffma2(p0.y, ww, a1);
                a2 = ffma2(p1.x, ww, a2);
                a3 = ffma2(p1.y, ww, a3);
            }
            float2 f;
            f = unpack2(a0); gsb[(r * 8 + 0) * 128 + jr] = f.x; gsb[(r * 8 + 1) * 128 + jr] = f.y;
            f = unpack2(a1); gsb[(r * 8 + 2) * 128 + jr] = f.x; gsb[(r * 8 + 3) * 128 + jr] = f.y;
            f = unpack2(a2); gsb[(r * 8 + 4) * 128 + jr] = f.x; gsb[(r * 8 + 5) * 128 + jr] = f.y;
            f = unpack2(a3); gsb[(r * 8 + 6) * 128 + jr] = f.x; gsb[(r * 8 + 7) * 128 + jr] = f.y;
        }
        __syncthreads();
        {
            float u = 0.f;
#pragma unroll
            for (int qq = 0; qq < 8; qq++) u += gsb[(qq * 8 + r) * 128 + jr];
            u_s[r * 128 + jr] = u;
        }
        __syncthreads();
        // ---- B: scores (warp per (row,t2) item), 800 items / 32 warps
        for (int n = 0; n < 25; n++) {
            int i = n * 32 + wp;
            int rr = i / 100;
            int t2 = i - rr * 100;
            const __nv_bfloat16* px = g_preX16 + (((size_t)(b0 + rr) * TTT + t2) << 7);
            float4 uv = *reinterpret_cast<const float4*>(&u_s[rr * 128 + lane * 4]);
            uint2 raw = *reinterpret_cast<const uint2*>(px + lane * 4);
            unsigned int rx = raw.x, ry = raw.y;
            __nv_bfloat162 p0 = *reinterpret_cast<__nv_bfloat162*>(&rx);
            __nv_bfloat162 p1 = *reinterpret_cast<__nv_bfloat162*>(&ry);
            float2 f0 = __bfloat1622float2(p0);
            float2 f1 = __bfloat1622float2(p1);
            float s = tanh_fast(f0.x + uv.x) * w2v.x + tanh_fast(f0.y + uv.y) * w2v.y
                    + tanh_fast(f1.x + uv.z) * w2v.z + tanh_fast(f1.y + uv.w) * w2v.w;
#pragma unroll
            for (int off = 16; off; off >>= 1) s += __shfl_xor_sync(0xffffffffu, s, off);
            if (lane == 0) scb[rr * 104 + t2] = s;
        }
        __syncthreads();
        // ---- C: softmax over t (warp per row)
        if (wp < 8) {
            float v0 = scb[wp * 104 + lane];
            float v1 = scb[wp * 104 + lane + 32];
            float v2 = scb[wp * 104 + lane + 64];
            float v3 = (lane < 4) ? scb[wp * 104 + lane + 96] : -1e30f;
            float mx = fmaxf(fmaxf(v0, v1), fmaxf(v2, v3));
#pragma unroll
            for (int off = 16; off; off >>= 1)
                mx = fmaxf(mx, __shfl_xor_sync(0xffffffffu, mx, off));
            float e0 = __expf(v0 - mx), e1 = __expf(v1 - mx), e2 = __expf(v2 - mx);
            float e3 = (lane < 4) ? __expf(v3 - mx) : 0.f;
            float ss = e0 + e1 + e2 + e3;
#pragma unroll
            for (int off = 16; off; off >>= 1) ss += __shfl_xor_sync(0xffffffffu, ss, off);
            float inv = 1.f / ss;
            scb[wp * 104 + lane] = e0 * inv;
            scb[wp * 104 + lane + 32] = e1 * inv;
            scb[wp * 104 + lane + 64] = e2 * inv;
            if (lane < 4) scb[wp * 104 + lane + 96] = e3 * inv;
        }
        __syncthreads();
        // ---- D: ctx = beta @ Xenc (thread = (r, col=jr))
        {
            const float* xb = g_Xenc + ((size_t)(b0 + r) * TTT) * HH + jr;
            const float* bp = scb + r * 104;
            float a0 = 0.f, a1 = 0.f;
#pragma unroll 4
            for (int t2 = 0; t2 < TTT; t2 += 2) {
                a0 += bp[t2] * xb[t2 * HH];
                a1 += bp[t2 + 1] * xb[(t2 + 1) * HH];
            }
            ctx_s[r * 128 + jr] = a0 + a1;
        }
        __syncthreads();
        // ---- y = ctx . fcW + fcb (warp per row)
        if (wp < 8) {
            float4 cv = *reinterpret_cast<const float4*>(&ctx_s[wp * 128 + lane * 4]);
            float s = cv.x * fwv.x + cv.y * fwv.y + cv.z * fwv.z + cv.w * fwv.w;
#pragma unroll
            for (int off = 16; off; off >>= 1) s += __shfl_xor_sync(0xffffffffu, s, off);
            if (lane == 0) y_s[wp] = s + fcb;
        }
        // ---- E: LSTM gates = d @ Whh^T (k halves by kh)
        {
            ull a0 = 0, a1 = 0, a2 = 0, a3 = 0;
            const float* wE = g_decWhhT + (kh * 64) * 512 + g;
            const float* dk = dcatT + (kh * 64) * 12;
#pragma unroll 4
            for (int kk = 0; kk < 64; kk++) {
                float w = wE[kk * 512];
                ull ww = pack2(w, w);
                ulonglong2 p0 = *reinterpret_cast<const ulonglong2*>(dk + kk * 12);
                ulonglong2 p1 = *reinterpret_cast<const ulonglong2*>(dk + kk * 12 + 4);
                a0 = ffma2(p0.x, ww, a0);
                a1 = ffma2(p0.y, ww, a1);
                a2 = ffma2(p1.x, ww, a2);
                a3 = ffma2(p1.y, ww, a3);
            }
            float2 f;
            f = unpack2(a0); gsb[kh * 4096 + 0 * 512 + g] = f.x; gsb[kh * 4096 + 1 * 512 + g] = f.y;
            f = unpack2(a1); gsb[kh * 4096 + 2 * 512 + g] = f.x; gsb[kh * 4096 + 3 * 512 + g] = f.y;
            f = unpack2(a2); gsb[kh * 4096 + 4 * 512 + g] = f.x; gsb[kh * 4096 + 5 * 512 + g] = f.y;
            f = unpack2(a3); gsb[kh * 4096 + 6 * 512 + g] = f.x; gsb[kh * 4096 + 7 * 512 + g] = f.y;
        }
        __syncthreads();
        // ---- F: state update for (r, jr)
        {
            float yv = y_s[r];
            float iv = gsb[r * 512 + jr      ] + gsb[4096 + r * 512 + jr      ] + yv * wih4[0] + bia4[0];
            float fv = gsb[r * 512 + jr + 128] + gsb[4096 + r * 512 + jr + 128] + yv * wih4[1] + bia4[1];
            float gv = gsb[r * 512 + jr + 256] + gsb[4096 + r * 512 + jr + 256] + yv * wih4[2] + bia4[2];
            float ov = gsb[r * 512 + jr + 384] + gsb[4096 + r * 512 + jr + 384] + yv * wih4[3] + bia4[3];
            float cn = sigm(fv) * c_reg + sigm(iv) * tanh_s(gv);
            float hn = sigm(ov) * tanh_s(cn);
            c_reg = cn;
            dcatT[jr * 12 + r] = hn;
            dcatT[(128 + jr) * 12 + r] = cn;
        }
        __syncthreads();
    }
    // ---- final FC: out = [d, ctx] @ fcfW^T + fcfb (stage fcfW into W1dcS region)
    for (int i = tid; i < CC * 256; i += 1024) {
        int cl = i >> 8, k = i & 255;
        W1dcS[cl * 257 + k] = fcfW[i];
    }
    __syncthreads();
    if (tid < 256) {
        int cl = tid & 31, rl = tid >> 5;
        float a = fcfB[cl];
#pragma unroll 8
        for (int k = 0; k < 128; k++) a += dcatT[k * 12 + rl] * W1dcS[cl * 257 + k];
#pragma unroll 8
        for (int k = 0; k < 128; k++) a += ctx_s[rl * 128 + k] * W1dcS[cl * 257 + 128 + k];
        out[(b0 + rl) * CC + cl] = a;
    }
}

// ---------------- host launcher ----------------
extern "C" void kernel_launch(void* const* d_in, const int* in_sizes, int n_in,
                              void* d_out, int out_size) {
    (void)in_sizes; (void)n_in; (void)out_size;
    const float* X       = (const float*)d_in[0];
    const float* encWih  = (const float*)d_in[1];
    const float* encWhh  = (const float*)d_in[2];
    const float* encBih  = (const float*)d_in[3];
    const float* encBhh  = (const float*)d_in[4];
    const float* encAttW = (const float*)d_in[5];
    // d_in[6] enc_attn_b: constant shift, drops out of softmax
    const float* decW1   = (const float*)d_in[7];
    const float* decB1   = (const float*)d_in[8];
    const float* decW2   = (const float*)d_in[9];
    // d_in[10] dec_b2: drops out of softmax
    const float* decWih  = (const float*)d_in[11];
    const float* decWhh  = (const float*)d_in[12];
    const float* decBih  = (const float*)d_in[13];
    const float* decBhh  = (const float*)d_in[14];
    const float* fcW     = (const float*)d_in[15];
    const float* fcB     = (const float*)d_in[16];
    const float* fcfW    = (const float*)d_in[17];
    const float* fcfB    = (const float*)d_in[18];
    float* out = (float*)d_out;

    cudaFuncSetAttribute(dec_fused, cudaFuncAttributeMaxDynamicSharedMemorySize,
                         DEC_SMEM_FLOATS * 4);

    prep<<<964, 256>>>(encWih, encWhh, decWhh, decW1, encBih, encBhh, decBih, decBhh);
    calc_alpha<<<BB, 128>>>(X, encAttW);
    enc_fused<<<BB / 8, 1024>>>(X);
    gemm_preX<<<BB * TTT / 64, 256>>>(decB1);
    dec_fused<<<BB / 8, 1024, DEC_SMEM_FLOATS * 4>>>(decWih, decW2, fcW, fcB, fcfW, fcfB, out);
}

// round 7
// speedup vs baseline: 2.4409x; 1.1049x over previous
#include <cuda_runtime.h>
#include <cuda_bf16.h>
#include <cstdint>

// Problem dims
#define BB 1024
#define TTT 100
#define MM 128
#define HH 128
#define PP 128
#define CC 32
#define GG 512   // 4H

// ---------------- device scratch (static, no allocation) ----------------
__device__ float g_alpha[BB * MM];
__device__ float g_Xenc[(size_t)BB * TTT * HH];             // 52.4 MB fp32 (preX GEMM + final ctx)
__device__ __nv_bfloat16 g_Xenc16[(size_t)BB * TTT * HH];   // 26.2 MB bf16 (ctx loop path)
__device__ __nv_bfloat16 g_preX16[(size_t)BB * TTT * HH];   // 26.2 MB bf16 (score path)
__device__ float g_encWcT[256 * GG];                        // [k][g]: k<128 Wih, k>=128 Whh
__device__ float g_decWhhT[128 * GG];                       // [k][g]
__device__ float g_W1dcT[256 * HH];                         // [k][h]
__device__ float g_W1xT[128 * HH];                          // [k][h]
__device__ float g_encBias[GG];
__device__ float g_decBias[GG];

// ---------------- helpers ----------------
typedef unsigned long long ull;

__device__ __forceinline__ ull pack2(float x, float y) {
    ull r;
    asm("mov.b64 %0, {%1, %2};" : "=l"(r)
        : "r"(__float_as_uint(x)), "r"(__float_as_uint(y)));
    return r;
}
__device__ __forceinline__ float2 unpack2(ull v) {
    unsigned int lo, hi;
    asm("mov.b64 {%0, %1}, %2;" : "=r"(lo), "=r"(hi) : "l"(v));
    return make_float2(__uint_as_float(lo), __uint_as_float(hi));
}
__device__ __forceinline__ ull ffma2(ull a, ull b, ull c) {
    ull d;
    asm("fma.rn.f32x2 %0, %1, %2, %3;" : "=l"(d) : "l"(a), "l"(b), "l"(c));
    return d;
}
__device__ __forceinline__ float sigm(float x) {
    return 1.0f / (1.0f + __expf(-x));
}
__device__ __forceinline__ float tanh_s(float x) {   // accurate tanh (exp-based)
    float a = fabsf(x);
    float e = __expf(-2.0f * a);
    float r = (1.0f - e) / (1.0f + e);
    return copysignf(r, x);
}
__device__ __forceinline__ float tanh_fast(float x) { // MUFU.TANH
    float y;
    asm("tanh.approx.f32 %0, %1;" : "=f"(y) : "f"(x));
    return y;
}

// ---------------- weight prep: transposes + combined biases ----------------
__global__ void prep(const float* __restrict__ encWih, const float* __restrict__ encWhh,
                     const float* __restrict__ decWhh, const float* __restrict__ decW1,
                     const float* __restrict__ ebih, const float* __restrict__ ebhh,
                     const float* __restrict__ dbih, const float* __restrict__ dbhh) {
    int idx = blockIdx.x * blockDim.x + threadIdx.x;
    if (idx < 131072) {                       // encWcT[k*512+g]
        int k = idx >> 9, gg = idx & 511;
        g_encWcT[idx] = (k < 128) ? encWih[gg * 128 + k] : encWhh[gg * 128 + (k - 128)];
    } else if (idx < 196608) {                // decWhhT[k*512+g]
        int l = idx - 131072; int k = l >> 9, gg = l & 511;
        g_decWhhT[l] = decWhh[gg * 128 + k];
    } else if (idx < 229376) {                // W1dcT[k*128+h] = decW1[h*384+k], k<256
        int l = idx - 196608; int hh = l & 127, k = l >> 7;
        g_W1dcT[l] = decW1[hh * 384 + k];
    } else if (idx < 245760) {                // W1xT[k*128+h] = decW1[h*384+256+k]
        int l = idx - 229376; int hh = l & 127, k = l >> 7;
        g_W1xT[l] = decW1[hh * 384 + 256 + k];
    } else if (idx < 246272) {
        int gg = idx - 245760; g_encBias[gg] = ebih[gg] + ebhh[gg];
    } else if (idx < 246784) {
        int gg = idx - 246272; g_decBias[gg] = dbih[gg] + dbhh[gg];
    }
}

// ---------------- alpha: softmax_m( sum_t X[b,t,m]*Wa[2H+t] ) ----------------
__global__ void calc_alpha(const float* __restrict__ X, const float* __restrict__ Wa) {
    __shared__ float wa[TTT];
    __shared__ float buf[MM];
    int b = blockIdx.x, m = threadIdx.x;
    if (m < TTT) wa[m] = Wa[2 * HH + m];
    __syncthreads();
    const float* xb = X + (size_t)b * TTT * MM + m;
    float a0 = 0.f, a1 = 0.f, a2 = 0.f, a3 = 0.f;
#pragma unroll
    for (int tt = 0; tt < TTT / 4; tt++) {
        a0 += xb[(tt * 4 + 0) * MM] * wa[tt * 4 + 0];
        a1 += xb[(tt * 4 + 1) * MM] * wa[tt * 4 + 1];
        a2 += xb[(tt * 4 + 2) * MM] * wa[tt * 4 + 2];
        a3 += xb[(tt * 4 + 3) * MM] * wa[tt * 4 + 3];
    }
    float s = (a0 + a1) + (a2 + a3);
    buf[m] = s; __syncthreads();
    for (int st = 64; st > 0; st >>= 1) {
        if (m < st) buf[m] = fmaxf(buf[m], buf[m + st]);
        __syncthreads();
    }
    float mx = buf[0]; __syncthreads();
    float e = __expf(s - mx);
    buf[m] = e; __syncthreads();
    for (int st = 64; st > 0; st >>= 1) {
        if (m < st) buf[m] += buf[m + st];
        __syncthreads();
    }
    g_alpha[b * MM + m] = e / buf[0];
}

// ---------------- fused encoder: 100-step recurrence, g-pair mapping ----------------
// GEMM thread: gp = tid&255 (g-pair), rh = (tid>>8)&1 (rows rh*4..+3), kh = tid>>9 (k half)
// per k: 1 LDS.128 (4 rows) + 1 LDG.64 (w pair) + 2 dup + 4 FFMA2
__global__ __launch_bounds__(1024, 1) void enc_fused(const float* __restrict__ X) {
    __shared__ float xhT[256][12];      // [k][row] transposed, stride 12 (16B-aligned rows)
    __shared__ float gsb[2][8][512];    // k-half partials [kh][row][g]
    const int b0 = blockIdx.x * 8;
    const int tid = threadIdx.x;
    const int gp = tid & 255;
    const int rh = (tid >> 8) & 1;
    const int kh = tid >> 9;
    const int g0 = gp * 2;
    const int rb = rh * 4;
    // nonlinearity mapping
    const int jr = tid & 127, r = tid >> 7;
    const float al = g_alpha[(b0 + r) * MM + jr];
    float bia4[4];
#pragma unroll
    for (int x = 0; x < 4; x++) bia4[x] = g_encBias[jr + 128 * x];
    float c_reg = 0.f;
    xhT[128 + jr][r] = 0.f;             // h0 = 0
    const size_t xrow = (size_t)(b0 + r) * TTT;
    float xv = X[xrow * MM + jr] * al;  // t=0 x_tilde
    const float2* wbase = reinterpret_cast<const float2*>(g_encWcT)
                          + (size_t)(kh * 128) * 256 + gp;

    for (int t = 0; t < TTT; t++) {
        xhT[jr][r] = xv;
        __syncthreads();
        int tn = (t < TTT - 1) ? t + 1 : t;
        float xnext = X[(xrow + tn) * MM + jr];

        ull a00 = 0, a01 = 0, a10 = 0, a11 = 0;   // [rowpair][gcol]
        const float* xp = &xhT[kh * 128][rb];
#pragma unroll 4
        for (int k = 0; k < 128; k++) {
            float2 w = wbase[(size_t)k * 256];
            ull w0 = pack2(w.x, w.x);
            ull w1 = pack2(w.y, w.y);
            ulonglong2 xr = *reinterpret_cast<const ulonglong2*>(xp + k * 12);
            a00 = ffma2(xr.x, w0, a00);
            a01 = ffma2(xr.x, w1, a01);
            a10 = ffma2(xr.y, w0, a10);
            a11 = ffma2(xr.y, w1, a11);
        }
        float2 f;
        f = unpack2(a00); gsb[kh][rb + 0][g0]     = f.x; gsb[kh][rb + 1][g0]     = f.y;
        f = unpack2(a01); gsb[kh][rb + 0][g0 + 1] = f.x; gsb[kh][rb + 1][g0 + 1] = f.y;
        f = unpack2(a10); gsb[kh][rb + 2][g0]     = f.x; gsb[kh][rb + 3][g0]     = f.y;
        f = unpack2(a11); gsb[kh][rb + 2][g0 + 1] = f.x; gsb[kh][rb + 3][g0 + 1] = f.y;
        __syncthreads();
        // nonlinearity for (r, jr)
        float iv = gsb[0][r][jr      ] + gsb[1][r][jr      ] + bia4[0];
        float fv = gsb[0][r][jr + 128] + gsb[1][r][jr + 128] + bia4[1];
        float gv = gsb[0][r][jr + 256] + gsb[1][r][jr + 256] + bia4[2];
        float ov = gsb[0][r][jr + 384] + gsb[1][r][jr + 384] + bia4[3];
        float cn = sigm(fv) * c_reg + sigm(iv) * tanh_s(gv);
        float hn = sigm(ov) * tanh_s(cn);
        c_reg = cn;
        xhT[128 + jr][r] = hn;
        g_Xenc[(xrow + t) * HH + jr] = hn;
        g_Xenc16[(xrow + t) * HH + jr] = __float2bfloat16(hn);
        xv = xnext * al;
    }
}

// ---------------- preX = Xenc @ W1x^T + b1 -> bf16 (f32x2 inner) ----------------
__global__ __launch_bounds__(256) void gemm_preX(const float* __restrict__ b1) {
    __shared__ float As[64][33];
    __shared__ float Ws[32][128];
    int n0 = blockIdx.x * 64;
    int tid = threadIdx.x;
    int tx = tid & 15, ty = tid >> 4;
    ull acc[4][4];
#pragma unroll
    for (int r = 0; r < 4; r++)
#pragma unroll
        for (int i = 0; i < 4; i++) acc[r][i] = 0;

    for (int kt = 0; kt < 4; kt++) {
        int k0 = kt * 32;
#pragma unroll
        for (int i = 0; i < 8; i++) {
            int idx = tid + i * 256;
            int r = idx >> 5, k = idx & 31;
            As[r][k] = g_Xenc[(size_t)(n0 + r) * HH + k0 + k];
        }
#pragma unroll
        for (int i = 0; i < 16; i++) {
            int idx = tid + i * 256;
            int k = idx >> 7, c = idx & 127;
            Ws[k][c] = g_W1xT[(k0 + k) * HH + c];
        }
        __syncthreads();
#pragma unroll
        for (int kk = 0; kk < 32; kk++) {
            ulonglong2 w0 = *reinterpret_cast<const ulonglong2*>(&Ws[kk][tx * 8]);
            ulonglong2 w1 = *reinterpret_cast<const ulonglong2*>(&Ws[kk][tx * 8 + 4]);
#pragma unroll
            for (int r = 0; r < 4; r++) {
                float av = As[ty * 4 + r][kk];
                ull avv = pack2(av, av);
                acc[r][0] = ffma2(avv, w0.x, acc[r][0]);
                acc[r][1] = ffma2(avv, w0.y, acc[r][1]);
                acc[r][2] = ffma2(avv, w1.x, acc[r][2]);
                acc[r][3] = ffma2(avv, w1.y, acc[r][3]);
            }
        }
        __syncthreads();
    }
#pragma unroll
    for (int r = 0; r < 4; r++) {
        int n = n0 + ty * 4 + r;
#pragma unroll
        for (int i = 0; i < 4; i++) {
            float2 f = unpack2(acc[r][i]);
            int c = tx * 8 + i * 2;
            g_preX16[(size_t)n * HH + c]     = __float2bfloat16(f.x + b1[c]);
            g_preX16[(size_t)n * HH + c + 1] = __float2bfloat16(f.y + b1[c + 1]);
        }
    }
}

// ---------------- fused decoder: warp-specialized, 100 steps + final FC ----------------
// smem floats:
//   W1dcS 32768 | dcatT 3072 | gsb 8192 (A partials / E partials) | u_s 1024 (also D partials)
//   ctx_s 1024 | scb 832 | y_s 8 | w2_s 128 | fw_s 128
#define DEC_SMEM_FLOATS (32768 + 3072 + 8192 + 1024 + 1024 + 832 + 8 + 128 + 128)

__global__ __launch_bounds__(1024, 1) void dec_fused(
    const float* __restrict__ decWih, const float* __restrict__ decW2,
    const float* __restrict__ fcW, const float* __restrict__ fcB,
    const float* __restrict__ fcfW, const float* __restrict__ fcfB,
    float* __restrict__ out)
{
    extern __shared__ float sm[];
    float* W1dcS = sm;
    float* dcatT = sm + 32768;
    float* gsb   = dcatT + 3072;
    float* u_s   = gsb + 8192;
    float* ctx_s = u_s + 1024;
    float* scb   = ctx_s + 1024;
    float* y_s   = scb + 832;
    float* w2_s  = y_s + 8;
    float* fw_s  = w2_s + 128;

    const int b0 = blockIdx.x * 8;
    const int tid = threadIdx.x;
    const int lane = tid & 31, wp = tid >> 5;
    const int jr = tid & 127;
    const int r  = tid >> 7;        // A: k-slice index; F: row
    // D mapping
    const int hp2 = (tid & 63) * 2;
    const int rr  = (tid >> 6) & 7;
    const int th  = tid >> 9;

    for (int i = tid; i < 32768; i += 1024) W1dcS[i] = g_W1dcT[i];
    for (int i = tid; i < 3072; i += 1024) dcatT[i] = 0.f;
    if (tid < 128) { w2_s[tid] = decW2[tid]; fw_s[tid] = fcW[tid]; }
    float wih4[4], bia4[4];
#pragma unroll
    for (int x = 0; x < 4; x++) {
        wih4[x] = decWih[jr + 128 * x];
        bia4[x] = g_decBias[jr + 128 * x];
    }
    float c_reg = 0.f;
    const float fcb = fcB[0];
    __syncthreads();
    const float4 w2v = *reinterpret_cast<const float4*>(&w2_s[lane * 4]);
    const float4 fwv = *reinterpret_cast<const float4*>(&fw_s[lane * 4]);

    for (int t = 0; t < TTT; t++) {
        // ---- A: u = [d;cc] @ W1dc^T (all warps; k-slice r*32..+31 per thread)
        {
            ull a0 = 0, a1 = 0, a2 = 0, a3 = 0;
            const float* wA = W1dcS + (r * 32) * 128 + jr;
            const float* dk = dcatT + (r * 32) * 12;
#pragma unroll 4
            for (int kk = 0; kk < 32; kk++) {
                float w = wA[kk * 128];
                ull ww = pack2(w, w);
                ulonglong2 p0 = *reinterpret_cast<const ulonglong2*>(dk + kk * 12);
                ulonglong2 p1 = *reinterpret_cast<const ulonglong2*>(dk + kk * 12 + 4);
                a0 = ffma2(p0.x, ww, a0);
                a1 = ffma2(p0.y, ww, a1);
                a2 = ffma2(p1.x, ww, a2);
                a3 = ffma2(p1.y, ww, a3);
            }
            float2 f;
            f = unpack2(a0); gsb[(r * 8 + 0) * 128 + jr] = f.x; gsb[(r * 8 + 1) * 128 + jr] = f.y;
            f = unpack2(a1); gsb[(r * 8 + 2) * 128 + jr] = f.x; gsb[(r * 8 + 3) * 128 + jr] = f.y;
            f = unpack2(a2); gsb[(r * 8 + 4) * 128 + jr] = f.x; gsb[(r * 8 + 5) * 128 + jr] = f.y;
            f = unpack2(a3); gsb[(r * 8 + 6) * 128 + jr] = f.x; gsb[(r * 8 + 7) * 128 + jr] = f.y;
        }
        __syncthreads();
        {
            float u = 0.f;
#pragma unroll
            for (int qq = 0; qq < 8; qq++) u += gsb[(qq * 8 + r) * 128 + jr];
            u_s[r * 128 + jr] = u;
        }
        __syncthreads();

        // ---- parallel: B+C on warps 0-15  |  E on warps 16-31
        if (tid < 512) {
            // B: 800 (row,t2) items over 16 warps
            for (int n = 0; n < 50; n++) {
                int i = n * 16 + wp;
                int br = i / 100;
                int t2 = i - br * 100;
                const __nv_bfloat16* px = g_preX16 + (((size_t)(b0 + br) * TTT + t2) << 7);
                float4 uv = *reinterpret_cast<const float4*>(&u_s[br * 128 + lane * 4]);
                uint2 raw = *reinterpret_cast<const uint2*>(px + lane * 4);
                unsigned int rx = raw.x, ry = raw.y;
                __nv_bfloat162 p0 = *reinterpret_cast<__nv_bfloat162*>(&rx);
                __nv_bfloat162 p1 = *reinterpret_cast<__nv_bfloat162*>(&ry);
                float2 f0 = __bfloat1622float2(p0);
                float2 f1 = __bfloat1622float2(p1);
                float s = tanh_fast(f0.x + uv.x) * w2v.x + tanh_fast(f0.y + uv.y) * w2v.y
                        + tanh_fast(f1.x + uv.z) * w2v.z + tanh_fast(f1.y + uv.w) * w2v.w;
#pragma unroll
                for (int off = 16; off; off >>= 1) s += __shfl_xor_sync(0xffffffffu, s, off);
                if (lane == 0) scb[br * 104 + t2] = s;
            }
            asm volatile("bar.sync 1, 512;" ::: "memory");
            // C: softmax over t (warps 0-7, one row each)
            if (wp < 8) {
                float v0 = scb[wp * 104 + lane];
                float v1 = scb[wp * 104 + lane + 32];
                float v2 = scb[wp * 104 + lane + 64];
                float v3 = (lane < 4) ? scb[wp * 104 + lane + 96] : -1e30f;
                float mx = fmaxf(fmaxf(v0, v1), fmaxf(v2, v3));
#pragma unroll
                for (int off = 16; off; off >>= 1)
                    mx = fmaxf(mx, __shfl_xor_sync(0xffffffffu, mx, off));
                float e0 = __expf(v0 - mx), e1 = __expf(v1 - mx), e2 = __expf(v2 - mx);
                float e3 = (lane < 4) ? __expf(v3 - mx) : 0.f;
                float ss = e0 + e1 + e2 + e3;
#pragma unroll
                for (int off = 16; off; off >>= 1) ss += __shfl_xor_sync(0xffffffffu, ss, off);
                float inv = 1.f / ss;
                scb[wp * 104 + lane] = e0 * inv;
                scb[wp * 104 + lane + 32] = e1 * inv;
                scb[wp * 104 + lane + 64] = e2 * inv;
                if (lane < 4) scb[wp * 104 + lane + 96] = e3 * inv;
            }
        } else {
            // E: gates = d @ Whh^T  (g-pair mapping on 512 threads)
            int ti = tid - 512;
            int gp = ti & 255, kh = ti >> 8;
            int g0 = gp * 2;
            ull e00 = 0, e01 = 0, e10 = 0, e11 = 0, e20 = 0, e21 = 0, e30 = 0, e31 = 0;
            const float2* wE = reinterpret_cast<const float2*>(g_decWhhT)
                               + (size_t)(kh * 64) * 256 + gp;
            const float* dk = dcatT + (kh * 64) * 12;
#pragma unroll 4
            for (int k = 0; k < 64; k++) {
                float2 w = wE[(size_t)k * 256];
                ull w0 = pack2(w.x, w.x);
                ull w1 = pack2(w.y, w.y);
                ulonglong2 p0 = *reinterpret_cast<const ulonglong2*>(dk + k * 12);
                ulonglong2 p1 = *reinterpret_cast<const ulonglong2*>(dk + k * 12 + 4);
                e00 = ffma2(p0.x, w0, e00); e01 = ffma2(p0.x, w1, e01);
                e10 = ffma2(p0.y, w0, e10); e11 = ffma2(p0.y, w1, e11);
                e20 = ffma2(p1.x, w0, e20); e21 = ffma2(p1.x, w1, e21);
                e30 = ffma2(p1.y, w0, e30); e31 = ffma2(p1.y, w1, e31);
            }
            float* gE = gsb + kh * 4096;
            float2 f;
            f = unpack2(e00); gE[0 * 512 + g0]     = f.x; gE[1 * 512 + g0]     = f.y;
            f = unpack2(e01); gE[0 * 512 + g0 + 1] = f.x; gE[1 * 512 + g0 + 1] = f.y;
            f = unpack2(e10); gE[2 * 512 + g0]     = f.x; gE[3 * 512 + g0]     = f.y;
            f = unpack2(e11); gE[2 * 512 + g0 + 1] = f.x; gE[3 * 512 + g0 + 1] = f.y;
            f = unpack2(e20); gE[4 * 512 + g0]     = f.x; gE[5 * 512 + g0]     = f.y;
            f = unpack2(e21); gE[4 * 512 + g0 + 1] = f.x; gE[5 * 512 + g0 + 1] = f.y;
            f = unpack2(e30); gE[6 * 512 + g0]     = f.x; gE[7 * 512 + g0]     = f.y;
            f = unpack2(e31); gE[6 * 512 + g0 + 1] = f.x; gE[7 * 512 + g0 + 1] = f.y;
        }
        __syncthreads();

        // ---- D: ctx = beta @ Xenc (bf16 for t<99, fp32 at t=99; t split in halves)
        {
            float a0 = 0.f, a1 = 0.f;
            const float* bp = scb + rr * 104 + th * 50;
            if (t != TTT - 1) {
                const __nv_bfloat16* xb = g_Xenc16
                    + ((size_t)(b0 + rr) * TTT + th * 50) * HH + hp2;
#pragma unroll 5
                for (int tt = 0; tt < 50; tt++) {
                    unsigned int raw = *reinterpret_cast<const unsigned int*>(xb + tt * HH);
                    __nv_bfloat162 p = *reinterpret_cast<__nv_bfloat162*>(&raw);
                    float2 fx = __bfloat1622float2(p);
                    float be = bp[tt];
                    a0 += be * fx.x; a1 += be * fx.y;
                }
            } else {
                const float* xb = g_Xenc
                    + ((size_t)(b0 + rr) * TTT + th * 50) * HH + hp2;
#pragma unroll 5
                for (int tt = 0; tt < 50; tt++) {
                    float2 fx = *reinterpret_cast<const float2*>(xb + tt * HH);
                    float be = bp[tt];
                    a0 += be * fx.x; a1 += be * fx.y;
                }
            }
            if (th == 1) {
                u_s[rr * 128 + hp2] = a0;
                u_s[rr * 128 + hp2 + 1] = a1;
            }
            __syncthreads();
            if (th == 0) {
                ctx_s[rr * 128 + hp2]     = a0 + u_s[rr * 128 + hp2];
                ctx_s[rr * 128 + hp2 + 1] = a1 + u_s[rr * 128 + hp2 + 1];
            }
        }
        __syncthreads();
        // ---- y = ctx . fcW + fcb (warp per row)
        if (wp < 8) {
            float4 cv = *reinterpret_cast<const float4*>(&ctx_s[wp * 128 + lane * 4]);
            float s = cv.x * fwv.x + cv.y * fwv.y + cv.z * fwv.z + cv.w * fwv.w;
#pragma unroll
            for (int off = 16; off; off >>= 1) s += __shfl_xor_sync(0xffffffffu, s, off);
            if (lane == 0) y_s[wp] = s + fcb;
        }
        __syncthreads();
        // ---- F: state update for (r, jr)
        {
            float yv = y_s[r];
            float iv = gsb[r * 512 + jr      ] + gsb[4096 + r * 512 + jr      ] + yv * wih4[0] + bia4[0];
            float fv = gsb[r * 512 + jr + 128] + gsb[4096 + r * 512 + jr + 128] + yv * wih4[1] + bia4[1];
            float gv = gsb[r * 512 + jr + 256] + gsb[4096 + r * 512 + jr + 256] + yv * wih4[2] + bia4[2];
            float ov = gsb[r * 512 + jr + 384] + gsb[4096 + r * 512 + jr + 384] + yv * wih4[3] + bia4[3];
            float cn = sigm(fv) * c_reg + sigm(iv) * tanh_s(gv);
            float hn = sigm(ov) * tanh_s(cn);
            c_reg = cn;
            dcatT[jr * 12 + r] = hn;
            dcatT[(128 + jr) * 12 + r] = cn;
        }
        __syncthreads();
    }
    // ---- final FC: out = [d, ctx] @ fcfW^T + fcfb
    for (int i = tid; i < CC * 256; i += 1024) {
        int cl = i >> 8, k = i & 255;
        W1dcS[cl * 257 + k] = fcfW[i];
    }
    __syncthreads();
    if (tid < 256) {
        int cl = tid & 31, rl = tid >> 5;
        float a = fcfB[cl];
#pragma unroll 8
        for (int k = 0; k < 128; k++) a += dcatT[k * 12 + rl] * W1dcS[cl * 257 + k];
#pragma unroll 8
        for (int k = 0; k < 128; k++) a += ctx_s[rl * 128 + k] * W1dcS[cl * 257 + 128 + k];
        out[(b0 + rl) * CC + cl] = a;
    }
}

// ---------------- host launcher ----------------
extern "C" void kernel_launch(void* const* d_in, const int* in_sizes, int n_in,
                              void* d_out, int out_size) {
    (void)in_sizes; (void)n_in; (void)out_size;
    const float* X       = (const float*)d_in[0];
    const float* encWih  = (const float*)d_in[1];
    const float* encWhh  = (const float*)d_in[2];
    const float* encBih  = (const float*)d_in[3];
    const float* encBhh  = (const float*)d_in[4];
    const float* encAttW = (const float*)d_in[5];
    // d_in[6] enc_attn_b: constant shift, drops out of softmax
    const float* decW1   = (const float*)d_in[7];
    const float* decB1   = (const float*)d_in[8];
    const float* decW2   = (const float*)d_in[9];
    // d_in[10] dec_b2: drops out of softmax
    const float* decWih  = (const float*)d_in[11];
    const float* decWhh  = (const float*)d_in[12];
    const float* decBih  = (const float*)d_in[13];
    const float* decBhh  = (const float*)d_in[14];
    const float* fcW     = (const float*)d_in[15];
    const float* fcB     = (const float*)d_in[16];
    const float* fcfW    = (const float*)d_in[17];
    const float* fcfB    = (const float*)d_in[18];
    float* out = (float*)d_out;

    cudaFuncSetAttribute(dec_fused, cudaFuncAttributeMaxDynamicSharedMemorySize,
                         DEC_SMEM_FLOATS * 4);

    prep<<<964, 256>>>(encWih, encWhh, decWhh, decW1, encBih, encBhh, decBih, decBhh);
    calc_alpha<<<BB, 128>>>(X, encAttW);
    enc_fused<<<BB / 8, 1024>>>(X);
    gemm_preX<<<BB * TTT / 64, 256>>>(decB1);
    dec_fused<<<BB / 8, 1024, DEC_SMEM_FLOATS * 4>>>(decWih, decW2, fcW, fcB, fcfW, fcfB, out);
}

// round 8
// speedup vs baseline: 2.7878x; 1.1421x over previous
#include <cuda_runtime.h>
#include <cuda_bf16.h>
#include <cstdint>

// Problem dims
#define BB 1024
#define TTT 100
#define MM 128
#define HH 128
#define PP 128
#define CC 32
#define GG 512   // 4H

// ---------------- device scratch (static, no allocation) ----------------
__device__ float g_alpha[BB * MM];
__device__ float g_Xenc[(size_t)BB * TTT * HH];             // fp32 (preX GEMM + final ctx)
__device__ __nv_bfloat16 g_Xenc16[(size_t)BB * TTT * HH];   // bf16 (ctx loop path)
__device__ __nv_bfloat16 g_preX16[(size_t)BB * TTT * HH];   // bf16 (score path)
__device__ float g_encWcT[256 * GG];                        // [k][g]: k<128 Wih, k>=128 Whh
__device__ float g_decWhhT[128 * GG];                       // [k][g]
__device__ float g_W1dcT[256 * HH];                         // [k][h]
__device__ float g_W1xT[128 * HH];                          // [k][h]
__device__ float g_encBias[GG];
__device__ float g_decBias[GG];

// ---------------- helpers ----------------
typedef unsigned long long ull;

__device__ __forceinline__ ull pack2(float x, float y) {
    ull r;
    asm("mov.b64 %0, {%1, %2};" : "=l"(r)
        : "r"(__float_as_uint(x)), "r"(__float_as_uint(y)));
    return r;
}
__device__ __forceinline__ float2 unpack2(ull v) {
    unsigned int lo, hi;
    asm("mov.b64 {%0, %1}, %2;" : "=r"(lo), "=r"(hi) : "l"(v));
    return make_float2(__uint_as_float(lo), __uint_as_float(hi));
}
__device__ __forceinline__ ull ffma2(ull a, ull b, ull c) {
    ull d;
    asm("fma.rn.f32x2 %0, %1, %2, %3;" : "=l"(d) : "l"(a), "l"(b), "l"(c));
    return d;
}
__device__ __forceinline__ float sigm(float x) {
    return 1.0f / (1.0f + __expf(-x));
}
__device__ __forceinline__ float tanh_s(float x) {   // accurate tanh (exp-based)
    float a = fabsf(x);
    float e = __expf(-2.0f * a);
    float r = (1.0f - e) / (1.0f + e);
    return copysignf(r, x);
}
__device__ __forceinline__ float tanh_fast(float x) { // MUFU.TANH
    float y;
    asm("tanh.approx.f32 %0, %1;" : "=f"(y) : "f"(x));
    return y;
}

// ---------------- weight prep: transposes + combined biases ----------------
__global__ void prep(const float* __restrict__ encWih, const float* __restrict__ encWhh,
                     const float* __restrict__ decWhh, const float* __restrict__ decW1,
                     const float* __restrict__ ebih, const float* __restrict__ ebhh,
                     const float* __restrict__ dbih, const float* __restrict__ dbhh) {
    int idx = blockIdx.x * blockDim.x + threadIdx.x;
    if (idx < 131072) {                       // encWcT[k*512+g]
        int k = idx >> 9, gg = idx & 511;
        g_encWcT[idx] = (k < 128) ? encWih[gg * 128 + k] : encWhh[gg * 128 + (k - 128)];
    } else if (idx < 196608) {                // decWhhT[k*512+g]
        int l = idx - 131072; int k = l >> 9, gg = l & 511;
        g_decWhhT[l] = decWhh[gg * 128 + k];
    } else if (idx < 229376) {                // W1dcT[k*128+h] = decW1[h*384+k], k<256
        int l = idx - 196608; int hh = l & 127, k = l >> 7;
        g_W1dcT[l] = decW1[hh * 384 + k];
    } else if (idx < 245760) {                // W1xT[k*128+h] = decW1[h*384+256+k]
        int l = idx - 229376; int hh = l & 127, k = l >> 7;
        g_W1xT[l] = decW1[hh * 384 + 256 + k];
    } else if (idx < 246272) {
        int gg = idx - 245760; g_encBias[gg] = ebih[gg] + ebhh[gg];
    } else if (idx < 246784) {
        int gg = idx - 246272; g_decBias[gg] = dbih[gg] + dbhh[gg];
    }
}

// ---------------- alpha: softmax_m( sum_t X[b,t,m]*Wa[2H+t] ) ----------------
__global__ void calc_alpha(const float* __restrict__ X, const float* __restrict__ Wa) {
    __shared__ float wa[TTT];
    __shared__ float buf[MM];
    int b = blockIdx.x, m = threadIdx.x;
    if (m < TTT) wa[m] = Wa[2 * HH + m];
    __syncthreads();
    const float* xb = X + (size_t)b * TTT * MM + m;
    float a0 = 0.f, a1 = 0.f, a2 = 0.f, a3 = 0.f;
#pragma unroll
    for (int tt = 0; tt < TTT / 4; tt++) {
        a0 += xb[(tt * 4 + 0) * MM] * wa[tt * 4 + 0];
        a1 += xb[(tt * 4 + 1) * MM] * wa[tt * 4 + 1];
        a2 += xb[(tt * 4 + 2) * MM] * wa[tt * 4 + 2];
        a3 += xb[(tt * 4 + 3) * MM] * wa[tt * 4 + 3];
    }
    float s = (a0 + a1) + (a2 + a3);
    buf[m] = s; __syncthreads();
    for (int st = 64; st > 0; st >>= 1) {
        if (m < st) buf[m] = fmaxf(buf[m], buf[m + st]);
        __syncthreads();
    }
    float mx = buf[0]; __syncthreads();
    float e = __expf(s - mx);
    buf[m] = e; __syncthreads();
    for (int st = 64; st > 0; st >>= 1) {
        if (m < st) buf[m] += buf[m + st];
        __syncthreads();
    }
    g_alpha[b * MM + m] = e / buf[0];
}

// ---------------- fused encoder: g-quad x row-quad x k-quarter mapping ----------------
// thread: gq = tid&127 (4 gate cols), rh = bit7 (4 rows), kq = bits8-9 (64 k)
// per k: 1 LDG.128 (4 weights) + 1 LDS.128 broadcast (4 rows) + 8 FFMA2
#define ENC_SMEM_FLOATS (3072 + 16384)
__global__ __launch_bounds__(1024, 1) void enc_fused(const float* __restrict__ X) {
    extern __shared__ float es[];
    float* xhT = es;            // [256][12]  [k][row]
    float* gsb = es + 3072;     // [4][8][512] k-quarter partials
    const int b0 = blockIdx.x * 8;
    const int tid = threadIdx.x;
    const int gq = tid & 127, rh = (tid >> 7) & 1, kq = tid >> 8;
    const int g0 = gq * 4, rb = rh * 4, kb = kq * 64;
    const int jr = tid & 127, r = tid >> 7;
    const float al = g_alpha[(b0 + r) * MM + jr];
    float bia4[4];
#pragma unroll
    for (int x = 0; x < 4; x++) bia4[x] = g_encBias[jr + 128 * x];
    float c_reg = 0.f;
    xhT[(128 + jr) * 12 + r] = 0.f;     // h0 = 0
    const size_t xrow = (size_t)(b0 + r) * TTT;
    float xv = X[xrow * MM + jr] * al;  // t=0 x_tilde
    const float4* wq = reinterpret_cast<const float4*>(g_encWcT) + (size_t)kb * 128 + gq;

    for (int t = 0; t < TTT; t++) {
        xhT[jr * 12 + r] = xv;
        __syncthreads();
        int tn = (t < TTT - 1) ? t + 1 : t;
        float xnext = X[(xrow + tn) * MM + jr];

        ull a00 = 0, a01 = 0, a10 = 0, a11 = 0, a20 = 0, a21 = 0, a30 = 0, a31 = 0;
        const float* xp = xhT + kb * 12 + rb;
#pragma unroll 4
        for (int k = 0; k < 64; k++) {
            float4 w = wq[(size_t)k * 128];
            ulonglong2 xr = *reinterpret_cast<const ulonglong2*>(xp + k * 12);
            ull w0 = pack2(w.x, w.x), w1 = pack2(w.y, w.y);
            ull w2 = pack2(w.z, w.z), w3 = pack2(w.w, w.w);
            a00 = ffma2(xr.x, w0, a00); a01 = ffma2(xr.y, w0, a01);
            a10 = ffma2(xr.x, w1, a10); a11 = ffma2(xr.y, w1, a11);
            a20 = ffma2(xr.x, w2, a20); a21 = ffma2(xr.y, w2, a21);
            a30 = ffma2(xr.x, w3, a30); a31 = ffma2(xr.y, w3, a31);
        }
        {
            float2 u00 = unpack2(a00), u10 = unpack2(a10), u20 = unpack2(a20), u30 = unpack2(a30);
            float2 u01 = unpack2(a01), u11 = unpack2(a11), u21 = unpack2(a21), u31 = unpack2(a31);
            float* gb = gsb + (kq * 8 + rb) * 512 + g0;
            *reinterpret_cast<float4*>(gb + 0 * 512) = make_float4(u00.x, u10.x, u20.x, u30.x);
            *reinterpret_cast<float4*>(gb + 1 * 512) = make_float4(u00.y, u10.y, u20.y, u30.y);
            *reinterpret_cast<float4*>(gb + 2 * 512) = make_float4(u01.x, u11.x, u21.x, u31.x);
            *reinterpret_cast<float4*>(gb + 3 * 512) = make_float4(u01.y, u11.y, u21.y, u31.y);
        }
        __syncthreads();
        // nonlinearity for (r, jr): sum 4 k-quarter partials
        float iv = gsb[(0 + r) * 512 + jr      ] + gsb[(8 + r) * 512 + jr      ]
                 + gsb[(16 + r) * 512 + jr     ] + gsb[(24 + r) * 512 + jr     ] + bia4[0];
        float fv = gsb[(0 + r) * 512 + jr + 128] + gsb[(8 + r) * 512 + jr + 128]
                 + gsb[(16 + r) * 512 + jr + 128] + gsb[(24 + r) * 512 + jr + 128] + bia4[1];
        float gv = gsb[(0 + r) * 512 + jr + 256] + gsb[(8 + r) * 512 + jr + 256]
                 + gsb[(16 + r) * 512 + jr + 256] + gsb[(24 + r) * 512 + jr + 256] + bia4[2];
        float ov = gsb[(0 + r) * 512 + jr + 384] + gsb[(8 + r) * 512 + jr + 384]
                 + gsb[(16 + r) * 512 + jr + 384] + gsb[(24 + r) * 512 + jr + 384] + bia4[3];
        float cn = sigm(fv) * c_reg + sigm(iv) * tanh_s(gv);
        float hn = sigm(ov) * tanh_s(cn);
        c_reg = cn;
        xhT[(128 + jr) * 12 + r] = hn;
        g_Xenc[(xrow + t) * HH + jr] = hn;
        g_Xenc16[(xrow + t) * HH + jr] = __float2bfloat16(hn);
        xv = xnext * al;
    }
}

// ---------------- preX = Xenc @ W1x^T + b1 -> bf16 (f32x2 inner) ----------------
__global__ __launch_bounds__(256) void gemm_preX(const float* __restrict__ b1) {
    __shared__ float As[64][33];
    __shared__ float Ws[32][128];
    int n0 = blockIdx.x * 64;
    int tid = threadIdx.x;
    int tx = tid & 15, ty = tid >> 4;
    ull acc[4][4];
#pragma unroll
    for (int r = 0; r < 4; r++)
#pragma unroll
        for (int i = 0; i < 4; i++) acc[r][i] = 0;

    for (int kt = 0; kt < 4; kt++) {
        int k0 = kt * 32;
#pragma unroll
        for (int i = 0; i < 8; i++) {
            int idx = tid + i * 256;
            int r = idx >> 5, k = idx & 31;
            As[r][k] = g_Xenc[(size_t)(n0 + r) * HH + k0 + k];
        }
#pragma unroll
        for (int i = 0; i < 16; i++) {
            int idx = tid + i * 256;
            int k = idx >> 7, c = idx & 127;
            Ws[k][c] = g_W1xT[(k0 + k) * HH + c];
        }
        __syncthreads();
#pragma unroll
        for (int kk = 0; kk < 32; kk++) {
            ulonglong2 w0 = *reinterpret_cast<const ulonglong2*>(&Ws[kk][tx * 8]);
            ulonglong2 w1 = *reinterpret_cast<const ulonglong2*>(&Ws[kk][tx * 8 + 4]);
#pragma unroll
            for (int r = 0; r < 4; r++) {
                float av = As[ty * 4 + r][kk];
                ull avv = pack2(av, av);
                acc[r][0] = ffma2(avv, w0.x, acc[r][0]);
                acc[r][1] = ffma2(avv, w0.y, acc[r][1]);
                acc[r][2] = ffma2(avv, w1.x, acc[r][2]);
                acc[r][3] = ffma2(avv, w1.y, acc[r][3]);
            }
        }
        __syncthreads();
    }
#pragma unroll
    for (int r = 0; r < 4; r++) {
        int n = n0 + ty * 4 + r;
#pragma unroll
        for (int i = 0; i < 4; i++) {
            float2 f = unpack2(acc[r][i]);
            int c = tx * 8 + i * 2;
            g_preX16[(size_t)n * HH + c]     = __float2bfloat16(f.x + b1[c]);
            g_preX16[(size_t)n * HH + c + 1] = __float2bfloat16(f.y + b1[c + 1]);
        }
    }
}

// ---------------- fused decoder: BCD single-pass + warp specialization ----------------
// smem floats:
//   W1dcS 32768 | dcatT 3072 | gsb 8192 (A partials / E partials) | u_s 1024
//   ctx_s 1024 | ctxp 2048 | zbuf 16 | y_s 8 | w2_s 128 | fw_s 128
#define DEC_SMEM_FLOATS (32768 + 3072 + 8192 + 1024 + 1024 + 2048 + 16 + 8 + 128 + 128)

__global__ __launch_bounds__(1024, 1) void dec_fused(
    const float* __restrict__ decWih, const float* __restrict__ decW2,
    const float* __restrict__ fcW, const float* __restrict__ fcB,
    const float* __restrict__ fcfW, const float* __restrict__ fcfB,
    float* __restrict__ out)
{
    extern __shared__ float sm[];
    float* W1dcS = sm;
    float* dcatT = sm + 32768;
    float* gsb   = dcatT + 3072;
    float* u_s   = gsb + 8192;
    float* ctx_s = u_s + 1024;
    float* ctxp  = ctx_s + 1024;
    float* zbuf  = ctxp + 2048;
    float* y_s   = zbuf + 16;
    float* w2_s  = y_s + 8;
    float* fw_s  = w2_s + 128;

    const int b0 = blockIdx.x * 8;
    const int tid = threadIdx.x;
    const int lane = tid & 31, wp = tid >> 5;
    const int jr = tid & 127;
    const int r  = tid >> 7;        // A: k-slice index; F: row

    for (int i = tid; i < 32768; i += 1024) W1dcS[i] = g_W1dcT[i];
    for (int i = tid; i < 3072; i += 1024) dcatT[i] = 0.f;
    if (tid < 128) { w2_s[tid] = decW2[tid]; fw_s[tid] = fcW[tid]; }
    float wih4[4], bia4[4];
#pragma unroll
    for (int x = 0; x < 4; x++) {
        wih4[x] = decWih[jr + 128 * x];
        bia4[x] = g_decBias[jr + 128 * x];
    }
    float c_reg = 0.f;
    const float fcb = fcB[0];
    // E-phase constants (threads 512..1023)
    const int ti = tid - 512;
    const int gqE = ti & 127, rhE = (ti >> 7) & 1, khE = (tid >= 512) ? (ti >> 8) : 0;
    const int g0E = gqE * 4, rbE = rhE * 4;
    const float4* wq4 = reinterpret_cast<const float4*>(g_decWhhT)
                        + (size_t)(khE * 64) * 128 + gqE;
    __syncthreads();
    const float4 w2v = *reinterpret_cast<const float4*>(&w2_s[lane * 4]);
    const float4 fwv = *reinterpret_cast<const float4*>(&fw_s[lane * 4]);

    for (int t = 0; t < TTT; t++) {
        // ---- A: u = [d;cc] @ W1dc^T (all warps; k-slice r*32..+31 per thread)
        {
            ull a0 = 0, a1 = 0, a2 = 0, a3 = 0;
            const float* wA = W1dcS + (r * 32) * 128 + jr;
            const float* dk = dcatT + (r * 32) * 12;
#pragma unroll 4
            for (int kk = 0; kk < 32; kk++) {
                float w = wA[kk * 128];
                ull ww = pack2(w, w);
                ulonglong2 p0 = *reinterpret_cast<const ulonglong2*>(dk + kk * 12);
                ulonglong2 p1 = *reinterpret_cast<const ulonglong2*>(dk + kk * 12 + 4);
                a0 = ffma2(p0.x, ww, a0);
                a1 = ffma2(p0.y, ww, a1);
                a2 = ffma2(p1.x, ww, a2);
                a3 = ffma2(p1.y, ww, a3);
            }
            float2 f;
            f = unpack2(a0); gsb[(r * 8 + 0) * 128 + jr] = f.x; gsb[(r * 8 + 1) * 128 + jr] = f.y;
            f = unpack2(a1); gsb[(r * 8 + 2) * 128 + jr] = f.x; gsb[(r * 8 + 3) * 128 + jr] = f.y;
            f = unpack2(a2); gsb[(r * 8 + 4) * 128 + jr] = f.x; gsb[(r * 8 + 5) * 128 + jr] = f.y;
            f = unpack2(a3); gsb[(r * 8 + 6) * 128 + jr] = f.x; gsb[(r * 8 + 7) * 128 + jr] = f.y;
        }
        __syncthreads();
        {
            float u = 0.f;
#pragma unroll
            for (int qq = 0; qq < 8; qq++) u += gsb[(qq * 8 + r) * 128 + jr];
            u_s[r * 128 + jr] = u;
        }
        __syncthreads();

        // ---- parallel: fused B+C+D on warps 0-15  |  E on warps 16-31
        if (tid < 512) {
            const int rw = wp & 7, fh = wp >> 3;
            float4 uv = *reinterpret_cast<const float4*>(&u_s[rw * 128 + lane * 4]);
            const __nv_bfloat16* pxb = g_preX16
                + ((size_t)(b0 + rw) * TTT + fh * 50) * HH + lane * 4;
            ull acc0 = 0, acc1 = 0;
            float zs = 0.f;
            if (t != TTT - 1) {
                const __nv_bfloat16* xeb = g_Xenc16
                    + ((size_t)(b0 + rw) * TTT + fh * 50) * HH + lane * 4;
#pragma unroll 2
                for (int tt = 0; tt < 50; tt++) {
                    uint2 pr = *reinterpret_cast<const uint2*>(pxb + tt * HH);
                    uint2 xr = *reinterpret_cast<const uint2*>(xeb + tt * HH);
                    __nv_bfloat162 pp0 = *reinterpret_cast<__nv_bfloat162*>(&pr.x);
                    __nv_bfloat162 pp1 = *reinterpret_cast<__nv_bfloat162*>(&pr.y);
                    float2 p0 = __bfloat1622float2(pp0);
                    float2 p1 = __bfloat1622float2(pp1);
                    float s = tanh_fast(p0.x + uv.x) * w2v.x + tanh_fast(p0.y + uv.y) * w2v.y
                            + tanh_fast(p1.x + uv.z) * w2v.z + tanh_fast(p1.y + uv.w) * w2v.w;
#pragma unroll
                    for (int off = 16; off; off >>= 1)
                        s += __shfl_xor_sync(0xffffffffu, s, off);
                    float e = __expf(s);      // |s| <= sum|w2| ~ 5 -> safe unnormalized
                    zs += e;
                    ull e2 = pack2(e, e);
                    __nv_bfloat162 xx0 = *reinterpret_cast<__nv_bfloat162*>(&xr.x);
                    __nv_bfloat162 xx1 = *reinterpret_cast<__nv_bfloat162*>(&xr.y);
                    float2 x0 = __bfloat1622float2(xx0);
                    float2 x1 = __bfloat1622float2(xx1);
                    acc0 = ffma2(pack2(x0.x, x0.y), e2, acc0);
                    acc1 = ffma2(pack2(x1.x, x1.y), e2, acc1);
                }
            } else {
                const float* xef = g_Xenc
                    + ((size_t)(b0 + rw) * TTT + fh * 50) * HH + lane * 4;
#pragma unroll 2
                for (int tt = 0; tt < 50; tt++) {
                    uint2 pr = *reinterpret_cast<const uint2*>(pxb + tt * HH);
                    float4 xf = *reinterpret_cast<const float4*>(xef + tt * HH);
                    __nv_bfloat162 pp0 = *reinterpret_cast<__nv_bfloat162*>(&pr.x);
                    __nv_bfloat162 pp1 = *reinterpret_cast<__nv_bfloat162*>(&pr.y);
                    float2 p0 = __bfloat1622float2(pp0);
                    float2 p1 = __bfloat1622float2(pp1);
                    float s = tanh_fast(p0.x + uv.x) * w2v.x + tanh_fast(p0.y + uv.y) * w2v.y
                            + tanh_fast(p1.x + uv.z) * w2v.z + tanh_fast(p1.y + uv.w) * w2v.w;
#pragma unroll
                    for (int off = 16; off; off >>= 1)
                        s += __shfl_xor_sync(0xffffffffu, s, off);
                    float e = __expf(s);
                    zs += e;
                    ull e2 = pack2(e, e);
                    acc0 = ffma2(pack2(xf.x, xf.y), e2, acc0);
                    acc1 = ffma2(pack2(xf.z, xf.w), e2, acc1);
                }
            }
            float2 c0 = unpack2(acc0), c1 = unpack2(acc1);
            *reinterpret_cast<float4*>(&ctxp[(fh * 8 + rw) * 128 + lane * 4]) =
                make_float4(c0.x, c0.y, c1.x, c1.y);
            if (lane == 0) zbuf[fh * 8 + rw] = zs;
        } else {
            // E: gates = d @ Whh^T  (g-quad x row-quad x k-half on 512 threads)
            ull e00 = 0, e01 = 0, e10 = 0, e11 = 0, e20 = 0, e21 = 0, e30 = 0, e31 = 0;
            const float* dk = dcatT + (khE * 64) * 12 + rbE;
#pragma unroll 4
            for (int k = 0; k < 64; k++) {
                float4 w = wq4[(size_t)k * 128];
                ulonglong2 xr = *reinterpret_cast<const ulonglong2*>(dk + k * 12);
                ull w0 = pack2(w.x, w.x), w1 = pack2(w.y, w.y);
                ull w2 = pack2(w.z, w.z), w3 = pack2(w.w, w.w);
                e00 = ffma2(xr.x, w0, e00); e01 = ffma2(xr.y, w0, e01);
                e10 = ffma2(xr.x, w1, e10); e11 = ffma2(xr.y, w1, e11);
                e20 = ffma2(xr.x, w2, e20); e21 = ffma2(xr.y, w2, e21);
                e30 = ffma2(xr.x, w3, e30); e31 = ffma2(xr.y, w3, e31);
            }
            float2 u00 = unpack2(e00), u10 = unpack2(e10), u20 = unpack2(e20), u30 = unpack2(e30);
            float2 u01 = unpack2(e01), u11 = unpack2(e11), u21 = unpack2(e21), u31 = unpack2(e31);
            float* gb = gsb + (khE * 8 + rbE) * 512 + g0E;
            *reinterpret_cast<float4*>(gb + 0 * 512) = make_float4(u00.x, u10.x, u20.x, u30.x);
            *reinterpret_cast<float4*>(gb + 1 * 512) = make_float4(u00.y, u10.y, u20.y, u30.y);
            *reinterpret_cast<float4*>(gb + 2 * 512) = make_float4(u01.x, u11.x, u21.x, u31.x);
            *reinterpret_cast<float4*>(gb + 3 * 512) = make_float4(u01.y, u11.y, u21.y, u31.y);
        }
        __syncthreads();

        // ---- ctx combine + y (warps 0-7, one row each)
        if (wp < 8) {
            float4 p0 = *reinterpret_cast<const float4*>(&ctxp[wp * 128 + lane * 4]);
            float4 p1 = *reinterpret_cast<const float4*>(&ctxp[1024 + wp * 128 + lane * 4]);
            float rz = __fdividef(1.f, zbuf[wp] + zbuf[8 + wp]);
            float4 cx = make_float4((p0.x + p1.x) * rz, (p0.y + p1.y) * rz,
                                    (p0.z + p1.z) * rz, (p0.w + p1.w) * rz);
            *reinterpret_cast<float4*>(&ctx_s[wp * 128 + lane * 4]) = cx;
            float s = cx.x * fwv.x + cx.y * fwv.y + cx.z * fwv.z + cx.w * fwv.w;
#pragma unroll
            for (int off = 16; off; off >>= 1) s += __shfl_xor_sync(0xffffffffu, s, off);
            if (lane == 0) y_s[wp] = s + fcb;
        }
        __syncthreads();
        // ---- F: state update for (r, jr)
        {
            float yv = y_s[r];
            float iv = gsb[(0 + r) * 512 + jr      ] + gsb[(8 + r) * 512 + jr      ] + yv * wih4[0] + bia4[0];
            float fv = gsb[(0 + r) * 512 + jr + 128] + gsb[(8 + r) * 512 + jr + 128] + yv * wih4[1] + bia4[1];
            float gv = gsb[(0 + r) * 512 + jr + 256] + gsb[(8 + r) * 512 + jr + 256] + yv * wih4[2] + bia4[2];
            float ov = gsb[(0 + r) * 512 + jr + 384] + gsb[(8 + r) * 512 + jr + 384] + yv * wih4[3] + bia4[3];
            float cn = sigm(fv) * c_reg + sigm(iv) * tanh_s(gv);
            float hn = sigm(ov) * tanh_s(cn);
            c_reg = cn;
            dcatT[jr * 12 + r] = hn;
            dcatT[(128 + jr) * 12 + r] = cn;
        }
        __syncthreads();
    }
    // ---- final FC: out = [d, ctx] @ fcfW^T + fcfb
    for (int i = tid; i < CC * 256; i += 1024) {
        int cl = i >> 8, k = i & 255;
        W1dcS[cl * 257 + k] = fcfW[i];
    }
    __syncthreads();
    if (tid < 256) {
        int cl = tid & 31, rl = tid >> 5;
        float a = fcfB[cl];
#pragma unroll 8
        for (int k = 0; k < 128; k++) a += dcatT[k * 12 + rl] * W1dcS[cl * 257 + k];
#pragma unroll 8
        for (int k = 0; k < 128; k++) a += ctx_s[rl * 128 + k] * W1dcS[cl * 257 + 128 + k];
        out[(b0 + rl) * CC + cl] = a;
    }
}

// ---------------- host launcher ----------------
extern "C" void kernel_launch(void* const* d_in, const int* in_sizes, int n_in,
                              void* d_out, int out_size) {
    (void)in_sizes; (void)n_in; (void)out_size;
    const float* X       = (const float*)d_in[0];
    const float* encWih  = (const float*)d_in[1];
    const float* encWhh  = (const float*)d_in[2];
    const float* encBih  = (const float*)d_in[3];
    const float* encBhh  = (const float*)d_in[4];
    const float* encAttW = (const float*)d_in[5];
    // d_in[6] enc_attn_b: constant shift, drops out of softmax
    const float* decW1   = (const float*)d_in[7];
    const float* decB1   = (const float*)d_in[8];
    const float* decW2   = (const float*)d_in[9];
    // d_in[10] dec_b2: drops out of softmax
    const float* decWih  = (const float*)d_in[11];
    const float* decWhh  = (const float*)d_in[12];
    const float* decBih  = (const float*)d_in[13];
    const float* decBhh  = (const float*)d_in[14];
    const float* fcW     = (const float*)d_in[15];
    const float* fcB     = (const float*)d_in[16];
    const float* fcfW    = (const float*)d_in[17];
    const float* fcfB    = (const float*)d_in[18];
    float* out = (float*)d_out;

    cudaFuncSetAttribute(enc_fused, cudaFuncAttributeMaxDynamicSharedMemorySize,
                         ENC_SMEM_FLOATS * 4);
    cudaFuncSetAttribute(dec_fused, cudaFuncAttributeMaxDynamicSharedMemorySize,
                         DEC_SMEM_FLOATS * 4);

    prep<<<964, 256>>>(encWih, encWhh, decWhh, decW1, encBih, encBhh, decBih, decBhh);
    calc_alpha<<<BB, 128>>>(X, encAttW);
    enc_fused<<<BB / 8, 1024, ENC_SMEM_FLOATS * 4>>>(X);
    gemm_preX<<<BB * TTT / 64, 256>>>(decB1);
    dec_fused<<<BB / 8, 1024, DEC_SMEM_FLOATS * 4>>>(decWih, decW2, fcW, fcB, fcfW, fcfB, out);
}

// round 9
// speedup vs baseline: 3.1438x; 1.1277x over previous
#include <cuda_runtime.h>
#include <cuda_bf16.h>
#include <cuda_fp16.h>
#include <cstdint>

// Problem dims
#define BB 1024
#define TTT 100
#define MM 128
#define HH 128
#define PP 128
#define CC 32
#define GG 512   // 4H

// ---------------- device scratch (static, no allocation) ----------------
__device__ float g_alpha[BB * MM];
__device__ float g_Xenc[(size_t)BB * TTT * HH];             // fp32 (preX GEMM + final ctx)
__device__ __nv_bfloat16 g_Xenc16[(size_t)BB * TTT * HH];   // bf16 (ctx loop path)
__device__ __nv_bfloat16 g_preX16[(size_t)BB * TTT * HH];   // bf16 (score path)
__device__ float g_encWcT[256 * GG];                        // [k][g]: k<128 Wih, k>=128 Whh
__device__ __half g_decWhh16[128 * GG];                     // [k][g] fp16 (E-phase stream)
__device__ float g_W1dcT[256 * HH];                         // [k][h]
__device__ float g_W1xT[128 * HH];                          // [k][h]
__device__ float g_encBias[GG];
__device__ float g_decBias[GG];

// ---------------- helpers ----------------
typedef unsigned long long ull;

__device__ __forceinline__ ull pack2(float x, float y) {
    ull r;
    asm("mov.b64 %0, {%1, %2};" : "=l"(r)
        : "r"(__float_as_uint(x)), "r"(__float_as_uint(y)));
    return r;
}
__device__ __forceinline__ float2 unpack2(ull v) {
    unsigned int lo, hi;
    asm("mov.b64 {%0, %1}, %2;" : "=r"(lo), "=r"(hi) : "l"(v));
    return make_float2(__uint_as_float(lo), __uint_as_float(hi));
}
__device__ __forceinline__ ull ffma2(ull a, ull b, ull c) {
    ull d;
    asm("fma.rn.f32x2 %0, %1, %2, %3;" : "=l"(d) : "l"(a), "l"(b), "l"(c));
    return d;
}
__device__ __forceinline__ float sigm(float x) {
    return 1.0f / (1.0f + __expf(-x));
}
__device__ __forceinline__ float tanh_s(float x) {   // accurate tanh (exp-based)
    float a = fabsf(x);
    float e = __expf(-2.0f * a);
    float r = (1.0f - e) / (1.0f + e);
    return copysignf(r, x);
}
__device__ __forceinline__ float tanh_fast(float x) { // MUFU.TANH
    float y;
    asm("tanh.approx.f32 %0, %1;" : "=f"(y) : "f"(x));
    return y;
}
__device__ __forceinline__ float2 bf2f(unsigned int u) {
    __nv_bfloat162 h = *reinterpret_cast<__nv_bfloat162*>(&u);
    return __bfloat1622float2(h);
}

// ---------------- weight prep: transposes + combined biases ----------------
__global__ void prep(const float* __restrict__ encWih, const float* __restrict__ encWhh,
                     const float* __restrict__ decWhh, const float* __restrict__ decW1,
                     const float* __restrict__ ebih, const float* __restrict__ ebhh,
                     const float* __restrict__ dbih, const float* __restrict__ dbhh) {
    int idx = blockIdx.x * blockDim.x + threadIdx.x;
    if (idx < 131072) {                       // encWcT[k*512+g]
        int k = idx >> 9, gg = idx & 511;
        g_encWcT[idx] = (k < 128) ? encWih[gg * 128 + k] : encWhh[gg * 128 + (k - 128)];
    } else if (idx < 196608) {                // decWhh16[k*512+g] (fp16)
        int l = idx - 131072; int k = l >> 9, gg = l & 511;
        g_decWhh16[l] = __float2half(decWhh[gg * 128 + k]);
    } else if (idx < 229376) {                // W1dcT[k*128+h] = decW1[h*384+k], k<256
        int l = idx - 196608; int hh = l & 127, k = l >> 7;
        g_W1dcT[l] = decW1[hh * 384 + k];
    } else if (idx < 245760) {                // W1xT[k*128+h] = decW1[h*384+256+k]
        int l = idx - 229376; int hh = l & 127, k = l >> 7;
        g_W1xT[l] = decW1[hh * 384 + 256 + k];
    } else if (idx < 246272) {
        int gg = idx - 245760; g_encBias[gg] = ebih[gg] + ebhh[gg];
    } else if (idx < 246784) {
        int gg = idx - 246272; g_decBias[gg] = dbih[gg] + dbhh[gg];
    }
}

// ---------------- alpha: softmax_m( sum_t X[b,t,m]*Wa[2H+t] ) ----------------
__global__ void calc_alpha(const float* __restrict__ X, const float* __restrict__ Wa) {
    __shared__ float wa[TTT];
    __shared__ float buf[MM];
    int b = blockIdx.x, m = threadIdx.x;
    if (m < TTT) wa[m] = Wa[2 * HH + m];
    __syncthreads();
    const float* xb = X + (size_t)b * TTT * MM + m;
    float a0 = 0.f, a1 = 0.f, a2 = 0.f, a3 = 0.f;
#pragma unroll
    for (int tt = 0; tt < TTT / 4; tt++) {
        a0 += xb[(tt * 4 + 0) * MM] * wa[tt * 4 + 0];
        a1 += xb[(tt * 4 + 1) * MM] * wa[tt * 4 + 1];
        a2 += xb[(tt * 4 + 2) * MM] * wa[tt * 4 + 2];
        a3 += xb[(tt * 4 + 3) * MM] * wa[tt * 4 + 3];
    }
    float s = (a0 + a1) + (a2 + a3);
    buf[m] = s; __syncthreads();
    for (int st = 64; st > 0; st >>= 1) {
        if (m < st) buf[m] = fmaxf(buf[m], buf[m + st]);
        __syncthreads();
    }
    float mx = buf[0]; __syncthreads();
    float e = __expf(s - mx);
    buf[m] = e; __syncthreads();
    for (int st = 64; st > 0; st >>= 1) {
        if (m < st) buf[m] += buf[m + st];
        __syncthreads();
    }
    g_alpha[b * MM + m] = e / buf[0];
}

// ---------------- fused encoder: g-quad x row-quad x k-quarter mapping ----------------
#define ENC_SMEM_FLOATS (3072 + 16384)
__global__ __launch_bounds__(1024, 1) void enc_fused(const float* __restrict__ X) {
    extern __shared__ float es[];
    float* xhT = es;            // [256][12]  [k][row]
    float* gsb = es + 3072;     // [4][8][512] k-quarter partials
    const int b0 = blockIdx.x * 8;
    const int tid = threadIdx.x;
    const int gq = tid & 127, rh = (tid >> 7) & 1, kq = tid >> 8;
    const int g0 = gq * 4, rb = rh * 4, kb = kq * 64;
    const int jr = tid & 127, r = tid >> 7;
    const float al = g_alpha[(b0 + r) * MM + jr];
    float bia4[4];
#pragma unroll
    for (int x = 0; x < 4; x++) bia4[x] = g_encBias[jr + 128 * x];
    float c_reg = 0.f;
    xhT[(128 + jr) * 12 + r] = 0.f;     // h0 = 0
    const size_t xrow = (size_t)(b0 + r) * TTT;
    float xv = X[xrow * MM + jr] * al;  // t=0 x_tilde
    const float4* wq = reinterpret_cast<const float4*>(g_encWcT) + (size_t)kb * 128 + gq;

    for (int t = 0; t < TTT; t++) {
        xhT[jr * 12 + r] = xv;
        __syncthreads();
        int tn = (t < TTT - 1) ? t + 1 : t;
        float xnext = X[(xrow + tn) * MM + jr];

        ull a00 = 0, a01 = 0, a10 = 0, a11 = 0, a20 = 0, a21 = 0, a30 = 0, a31 = 0;
        const float* xp = xhT + kb * 12 + rb;
#pragma unroll 4
        for (int k = 0; k < 64; k++) {
            float4 w = wq[(size_t)k * 128];
            ulonglong2 xr = *reinterpret_cast<const ulonglong2*>(xp + k * 12);
            ull w0 = pack2(w.x, w.x), w1 = pack2(w.y, w.y);
            ull w2 = pack2(w.z, w.z), w3 = pack2(w.w, w.w);
            a00 = ffma2(xr.x, w0, a00); a01 = ffma2(xr.y, w0, a01);
            a10 = ffma2(xr.x, w1, a10); a11 = ffma2(xr.y, w1, a11);
            a20 = ffma2(xr.x, w2, a20); a21 = ffma2(xr.y, w2, a21);
            a30 = ffma2(xr.x, w3, a30); a31 = ffma2(xr.y, w3, a31);
        }
        {
            float2 u00 = unpack2(a00), u10 = unpack2(a10), u20 = unpack2(a20), u30 = unpack2(a30);
            float2 u01 = unpack2(a01), u11 = unpack2(a11), u21 = unpack2(a21), u31 = unpack2(a31);
            float* gb = gsb + (kq * 8 + rb) * 512 + g0;
            *reinterpret_cast<float4*>(gb + 0 * 512) = make_float4(u00.x, u10.x, u20.x, u30.x);
            *reinterpret_cast<float4*>(gb + 1 * 512) = make_float4(u00.y, u10.y, u20.y, u30.y);
            *reinterpret_cast<float4*>(gb + 2 * 512) = make_float4(u01.x, u11.x, u21.x, u31.x);
            *reinterpret_cast<float4*>(gb + 3 * 512) = make_float4(u01.y, u11.y, u21.y, u31.y);
        }
        __syncthreads();
        // nonlinearity for (r, jr): sum 4 k-quarter partials
        float iv = gsb[(0 + r) * 512 + jr      ] + gsb[(8 + r) * 512 + jr      ]
                 + gsb[(16 + r) * 512 + jr     ] + gsb[(24 + r) * 512 + jr     ] + bia4[0];
        float fv = gsb[(0 + r) * 512 + jr + 128] + gsb[(8 + r) * 512 + jr + 128]
                 + gsb[(16 + r) * 512 + jr + 128] + gsb[(24 + r) * 512 + jr + 128] + bia4[1];
        float gv = gsb[(0 + r) * 512 + jr + 256] + gsb[(8 + r) * 512 + jr + 256]
                 + gsb[(16 + r) * 512 + jr + 256] + gsb[(24 + r) * 512 + jr + 256] + bia4[2];
        float ov = gsb[(0 + r) * 512 + jr + 384] + gsb[(8 + r) * 512 + jr + 384]
                 + gsb[(16 + r) * 512 + jr + 384] + gsb[(24 + r) * 512 + jr + 384] + bia4[3];
        float cn = sigm(fv) * c_reg + sigm(iv) * tanh_s(gv);
        float hn = sigm(ov) * tanh_s(cn);
        c_reg = cn;
        xhT[(128 + jr) * 12 + r] = hn;
        g_Xenc[(xrow + t) * HH + jr] = hn;
        g_Xenc16[(xrow + t) * HH + jr] = __float2bfloat16(hn);
        xv = xnext * al;
    }
}

// ---------------- preX = Xenc @ W1x^T + b1 -> bf16 (f32x2 inner) ----------------
__global__ __launch_bounds__(256) void gemm_preX(const float* __restrict__ b1) {
    __shared__ float As[64][33];
    __shared__ float Ws[32][128];
    int n0 = blockIdx.x * 64;
    int tid = threadIdx.x;
    int tx = tid & 15, ty = tid >> 4;
    ull acc[4][4];
#pragma unroll
    for (int r = 0; r < 4; r++)
#pragma unroll
        for (int i = 0; i < 4; i++) acc[r][i] = 0;

    for (int kt = 0; kt < 4; kt++) {
        int k0 = kt * 32;
#pragma unroll
        for (int i = 0; i < 8; i++) {
            int idx = tid + i * 256;
            int r = idx >> 5, k = idx & 31;
            As[r][k] = g_Xenc[(size_t)(n0 + r) * HH + k0 + k];
        }
#pragma unroll
        for (int i = 0; i < 16; i++) {
            int idx = tid + i * 256;
            int k = idx >> 7, c = idx & 127;
            Ws[k][c] = g_W1xT[(k0 + k) * HH + c];
        }
        __syncthreads();
#pragma unroll
        for (int kk = 0; kk < 32; kk++) {
            ulonglong2 w0 = *reinterpret_cast<const ulonglong2*>(&Ws[kk][tx * 8]);
            ulonglong2 w1 = *reinterpret_cast<const ulonglong2*>(&Ws[kk][tx * 8 + 4]);
#pragma unroll
            for (int r = 0; r < 4; r++) {
                float av = As[ty * 4 + r][kk];
                ull avv = pack2(av, av);
                acc[r][0] = ffma2(avv, w0.x, acc[r][0]);
                acc[r][1] = ffma2(avv, w0.y, acc[r][1]);
                acc[r][2] = ffma2(avv, w1.x, acc[r][2]);
                acc[r][3] = ffma2(avv, w1.y, acc[r][3]);
            }
        }
        __syncthreads();
    }
#pragma unroll
    for (int r = 0; r < 4; r++) {
        int n = n0 + ty * 4 + r;
#pragma unroll
        for (int i = 0; i < 4; i++) {
            float2 f = unpack2(acc[r][i]);
            int c = tx * 8 + i * 2;
            g_preX16[(size_t)n * HH + c]     = __float2bfloat16(f.x + b1[c]);
            g_preX16[(size_t)n * HH + c + 1] = __float2bfloat16(f.y + b1[c + 1]);
        }
    }
}

// ---------------- fused decoder: BCD single-pass (ILP2) + warp specialization ----------
// smem floats:
//   W1dcS 32768 | dcatT 3072 | gsb 8192 (A partials / E partials) | u_s 1024
//   ctx_s 1024 | ctxp 2048 | zbuf 16 | y_s 8 | w2_s 128 | fw_s 128
#define DEC_SMEM_FLOATS (32768 + 3072 + 8192 + 1024 + 1024 + 2048 + 16 + 8 + 128 + 128)

__global__ __launch_bounds__(1024, 1) void dec_fused(
    const float* __restrict__ decWih, const float* __restrict__ decW2,
    const float* __restrict__ fcW, const float* __restrict__ fcB,
    const float* __restrict__ fcfW, const float* __restrict__ fcfB,
    float* __restrict__ out)
{
    extern __shared__ float sm[];
    float* W1dcS = sm;
    float* dcatT = sm + 32768;
    float* gsb   = dcatT + 3072;
    float* u_s   = gsb + 8192;
    float* ctx_s = u_s + 1024;
    float* ctxp  = ctx_s + 1024;
    float* zbuf  = ctxp + 2048;
    float* y_s   = zbuf + 16;
    float* w2_s  = y_s + 8;
    float* fw_s  = w2_s + 128;

    const int b0 = blockIdx.x * 8;
    const int tid = threadIdx.x;
    const int lane = tid & 31, wp = tid >> 5;
    const int jr = tid & 127;
    const int r  = tid >> 7;        // A: k-slice index; F: row

    for (int i = tid; i < 32768; i += 1024) W1dcS[i] = g_W1dcT[i];
    for (int i = tid; i < 3072; i += 1024) dcatT[i] = 0.f;
    if (tid < 128) { w2_s[tid] = decW2[tid]; fw_s[tid] = fcW[tid]; }
    float wih4[4], bia4[4];
#pragma unroll
    for (int x = 0; x < 4; x++) {
        wih4[x] = decWih[jr + 128 * x];
        bia4[x] = g_decBias[jr + 128 * x];
    }
    float c_reg = 0.f;
    const float fcb = fcB[0];
    // E-phase constants (threads 512..1023)
    const int ti = tid - 512;
    const int gqE = ti & 127, rhE = (ti >> 7) & 1, khE = (tid >= 512) ? (ti >> 8) : 0;
    const int g0E = gqE * 4, rbE = rhE * 4;
    const uint2* wqh = reinterpret_cast<const uint2*>(g_decWhh16)
                       + (size_t)(khE * 64) * 128 + gqE;
    __syncthreads();
    const float4 w2v = *reinterpret_cast<const float4*>(&w2_s[lane * 4]);
    const float4 fwv = *reinterpret_cast<const float4*>(&fw_s[lane * 4]);

    for (int t = 0; t < TTT; t++) {
        // ---- A: u = [d;cc] @ W1dc^T (all warps; k-slice r*32..+31 per thread)
        {
            ull a0 = 0, a1 = 0, a2 = 0, a3 = 0;
            const float* wA = W1dcS + (r * 32) * 128 + jr;
            const float* dk = dcatT + (r * 32) * 12;
#pragma unroll 4
            for (int kk = 0; kk < 32; kk++) {
                float w = wA[kk * 128];
                ull ww = pack2(w, w);
                ulonglong2 p0 = *reinterpret_cast<const ulonglong2*>(dk + kk * 12);
                ulonglong2 p1 = *reinterpret_cast<const ulonglong2*>(dk + kk * 12 + 4);
                a0 = ffma2(p0.x, ww, a0);
                a1 = ffma2(p0.y, ww, a1);
                a2 = ffma2(p1.x, ww, a2);
                a3 = ffma2(p1.y, ww, a3);
            }
            float2 f;
            f = unpack2(a0); gsb[(r * 8 + 0) * 128 + jr] = f.x; gsb[(r * 8 + 1) * 128 + jr] = f.y;
            f = unpack2(a1); gsb[(r * 8 + 2) * 128 + jr] = f.x; gsb[(r * 8 + 3) * 128 + jr] = f.y;
            f = unpack2(a2); gsb[(r * 8 + 4) * 128 + jr] = f.x; gsb[(r * 8 + 5) * 128 + jr] = f.y;
            f = unpack2(a3); gsb[(r * 8 + 6) * 128 + jr] = f.x; gsb[(r * 8 + 7) * 128 + jr] = f.y;
        }
        __syncthreads();
        {
            float u = 0.f;
#pragma unroll
            for (int qq = 0; qq < 8; qq++) u += gsb[(qq * 8 + r) * 128 + jr];
            u_s[r * 128 + jr] = u;
        }
        __syncthreads();

        // ---- parallel: fused B+C+D (ILP2) on warps 0-15  |  E on warps 16-31
        if (tid < 512) {
            const int rw = wp & 7, fh = wp >> 3;
            float4 uv = *reinterpret_cast<const float4*>(&u_s[rw * 128 + lane * 4]);
            const __nv_bfloat16* pxb = g_preX16
                + ((size_t)(b0 + rw) * TTT + fh * 50) * HH + lane * 4;
            ull acc0 = 0, acc1 = 0;
            float zs = 0.f;
            if (t != TTT - 1) {
                const __nv_bfloat16* xeb = g_Xenc16
                    + ((size_t)(b0 + rw) * TTT + fh * 50) * HH + lane * 4;
                for (int n = 0; n < 25; n++) {
                    uint2 prA = *reinterpret_cast<const uint2*>(pxb + (2 * n) * HH);
                    uint2 prB = *reinterpret_cast<const uint2*>(pxb + (2 * n + 1) * HH);
                    uint2 xrA = *reinterpret_cast<const uint2*>(xeb + (2 * n) * HH);
                    uint2 xrB = *reinterpret_cast<const uint2*>(xeb + (2 * n + 1) * HH);
                    float2 pA0 = bf2f(prA.x), pA1 = bf2f(prA.y);
                    float2 pB0 = bf2f(prB.x), pB1 = bf2f(prB.y);
                    float sA = tanh_fast(pA0.x + uv.x) * w2v.x + tanh_fast(pA0.y + uv.y) * w2v.y
                             + tanh_fast(pA1.x + uv.z) * w2v.z + tanh_fast(pA1.y + uv.w) * w2v.w;
                    float sB = tanh_fast(pB0.x + uv.x) * w2v.x + tanh_fast(pB0.y + uv.y) * w2v.y
                             + tanh_fast(pB1.x + uv.z) * w2v.z + tanh_fast(pB1.y + uv.w) * w2v.w;
#pragma unroll
                    for (int off = 16; off; off >>= 1) {
                        sA += __shfl_xor_sync(0xffffffffu, sA, off);
                        sB += __shfl_xor_sync(0xffffffffu, sB, off);
                    }
                    float eA = __expf(sA), eB = __expf(sB);   // |s| bounded -> safe
                    zs += eA + eB;
                    ull eA2 = pack2(eA, eA), eB2 = pack2(eB, eB);
                    float2 xA0 = bf2f(xrA.x), xA1 = bf2f(xrA.y);
                    float2 xB0 = bf2f(xrB.x), xB1 = bf2f(xrB.y);
                    acc0 = ffma2(pack2(xA0.x, xA0.y), eA2, acc0);
                    acc1 = ffma2(pack2(xA1.x, xA1.y), eA2, acc1);
                    acc0 = ffma2(pack2(xB0.x, xB0.y), eB2, acc0);
                    acc1 = ffma2(pack2(xB1.x, xB1.y), eB2, acc1);
                }
            } else {
                const float* xef = g_Xenc
                    + ((size_t)(b0 + rw) * TTT + fh * 50) * HH + lane * 4;
                for (int n = 0; n < 25; n++) {
                    uint2 prA = *reinterpret_cast<const uint2*>(pxb + (2 * n) * HH);
                    uint2 prB = *reinterpret_cast<const uint2*>(pxb + (2 * n + 1) * HH);
                    float4 xfA = *reinterpret_cast<const float4*>(xef + (2 * n) * HH);
                    float4 xfB = *reinterpret_cast<const float4*>(xef + (2 * n + 1) * HH);
                    float2 pA0 = bf2f(prA.x), pA1 = bf2f(prA.y);
                    float2 pB0 = bf2f(prB.x), pB1 = bf2f(prB.y);
                    float sA = tanh_fast(pA0.x + uv.x) * w2v.x + tanh_fast(pA0.y + uv.y) * w2v.y
                             + tanh_fast(pA1.x + uv.z) * w2v.z + tanh_fast(pA1.y + uv.w) * w2v.w;
                    float sB = tanh_fast(pB0.x + uv.x) * w2v.x + tanh_fast(pB0.y + uv.y) * w2v.y
                             + tanh_fast(pB1.x + uv.z) * w2v.z + tanh_fast(pB1.y + uv.w) * w2v.w;
#pragma unroll
                    for (int off = 16; off; off >>= 1) {
                        sA += __shfl_xor_sync(0xffffffffu, sA, off);
                        sB += __shfl_xor_sync(0xffffffffu, sB, off);
                    }
                    float eA = __expf(sA), eB = __expf(sB);
                    zs += eA + eB;
                    ull eA2 = pack2(eA, eA), eB2 = pack2(eB, eB);
                    acc0 = ffma2(pack2(xfA.x, xfA.y), eA2, acc0);
                    acc1 = ffma2(pack2(xfA.z, xfA.w), eA2, acc1);
                    acc0 = ffma2(pack2(xfB.x, xfB.y), eB2, acc0);
                    acc1 = ffma2(pack2(xfB.z, xfB.w), eB2, acc1);
                }
            }
            float2 c0 = unpack2(acc0), c1 = unpack2(acc1);
            *reinterpret_cast<float4*>(&ctxp[(fh * 8 + rw) * 128 + lane * 4]) =
                make_float4(c0.x, c0.y, c1.x, c1.y);
            if (lane == 0) zbuf[fh * 8 + rw] = zs;
        } else {
            // E: gates = d @ Whh^T  (fp16 weights, g-quad x row-quad x k-half)
            ull e00 = 0, e01 = 0, e10 = 0, e11 = 0, e20 = 0, e21 = 0, e30 = 0, e31 = 0;
            const float* dk = dcatT + (khE * 64) * 12 + rbE;
#pragma unroll 4
            for (int k = 0; k < 64; k++) {
                uint2 wr = wqh[(size_t)k * 128];
                __half2 hA = *reinterpret_cast<const __half2*>(&wr.x);
                __half2 hB = *reinterpret_cast<const __half2*>(&wr.y);
                float2 wa = __half22float2(hA);
                float2 wb = __half22float2(hB);
                ulonglong2 xr = *reinterpret_cast<const ulonglong2*>(dk + k * 12);
                ull w0 = pack2(wa.x, wa.x), w1 = pack2(wa.y, wa.y);
                ull w2 = pack2(wb.x, wb.x), w3 = pack2(wb.y, wb.y);
                e00 = ffma2(xr.x, w0, e00); e01 = ffma2(xr.y, w0, e01);
                e10 = ffma2(xr.x, w1, e10); e11 = ffma2(xr.y, w1, e11);
                e20 = ffma2(xr.x, w2, e20); e21 = ffma2(xr.y, w2, e21);
                e30 = ffma2(xr.x, w3, e30); e31 = ffma2(xr.y, w3, e31);
            }
            float2 u00 = unpack2(e00), u10 = unpack2(e10), u20 = unpack2(e20), u30 = unpack2(e30);
            float2 u01 = unpack2(e01), u11 = unpack2(e11), u21 = unpack2(e21), u31 = unpack2(e31);
            float* gb = gsb + (khE * 8 + rbE) * 512 + g0E;
            *reinterpret_cast<float4*>(gb + 0 * 512) = make_float4(u00.x, u10.x, u20.x, u30.x);
            *reinterpret_cast<float4*>(gb + 1 * 512) = make_float4(u00.y, u10.y, u20.y, u30.y);
            *reinterpret_cast<float4*>(gb + 2 * 512) = make_float4(u01.x, u11.x, u21.x, u31.x);
            *reinterpret_cast<float4*>(gb + 3 * 512) = make_float4(u01.y, u11.y, u21.y, u31.y);
        }
        __syncthreads();

        // ---- ctx combine + y (warps 0-7, one row each)
        if (wp < 8) {
            float4 p0 = *reinterpret_cast<const float4*>(&ctxp[wp * 128 + lane * 4]);
            float4 p1 = *reinterpret_cast<const float4*>(&ctxp[1024 + wp * 128 + lane * 4]);
            float rz = __fdividef(1.f, zbuf[wp] + zbuf[8 + wp]);
            float4 cx = make_float4((p0.x + p1.x) * rz, (p0.y + p1.y) * rz,
                                    (p0.z + p1.z) * rz, (p0.w + p1.w) * rz);
            *reinterpret_cast<float4*>(&ctx_s[wp * 128 + lane * 4]) = cx;
            float s = cx.x * fwv.x + cx.y * fwv.y + cx.z * fwv.z + cx.w * fwv.w;
#pragma unroll
            for (int off = 16; off; off >>= 1) s += __shfl_xor_sync(0xffffffffu, s, off);
            if (lane == 0) y_s[wp] = s + fcb;
        }
        __syncthreads();
        // ---- F: state update for (r, jr)
        {
            float yv = y_s[r];
            float iv = gsb[(0 + r) * 512 + jr      ] + gsb[(8 + r) * 512 + jr      ] + yv * wih4[0] + bia4[0];
            float fv = gsb[(0 + r) * 512 + jr + 128] + gsb[(8 + r) * 512 + jr + 128] + yv * wih4[1] + bia4[1];
            float gv = gsb[(0 + r) * 512 + jr + 256] + gsb[(8 + r) * 512 + jr + 256] + yv * wih4[2] + bia4[2];
            float ov = gsb[(0 + r) * 512 + jr + 384] + gsb[(8 + r) * 512 + jr + 384] + yv * wih4[3] + bia4[3];
            float cn = sigm(fv) * c_reg + sigm(iv) * tanh_s(gv);
            float hn = sigm(ov) * tanh_s(cn);
            c_reg = cn;
            dcatT[jr * 12 + r] = hn;
            dcatT[(128 + jr) * 12 + r] = cn;
        }
        __syncthreads();
    }
    // ---- final FC: out = [d, ctx] @ fcfW^T + fcfb
    for (int i = tid; i < CC * 256; i += 1024) {
        int cl = i >> 8, k = i & 255;
        W1dcS[cl * 257 + k] = fcfW[i];
    }
    __syncthreads();
    if (tid < 256) {
        int cl = tid & 31, rl = tid >> 5;
        float a = fcfB[cl];
#pragma unroll 8
        for (int k = 0; k < 128; k++) a += dcatT[k * 12 + rl] * W1dcS[cl * 257 + k];
#pragma unroll 8
        for (int k = 0; k < 128; k++) a += ctx_s[rl * 128 + k] * W1dcS[cl * 257 + 128 + k];
        out[(b0 + rl) * CC + cl] = a;
    }
}

// ---------------- host launcher ----------------
extern "C" void kernel_launch(void* const* d_in, const int* in_sizes, int n_in,
                              void* d_out, int out_size) {
    (void)in_sizes; (void)n_in; (void)out_size;
    const float* X       = (const float*)d_in[0];
    const float* encWih  = (const float*)d_in[1];
    const float* encWhh  = (const float*)d_in[2];
    const float* encBih  = (const float*)d_in[3];
    const float* encBhh  = (const float*)d_in[4];
    const float* encAttW = (const float*)d_in[5];
    // d_in[6] enc_attn_b: constant shift, drops out of softmax
    const float* decW1   = (const float*)d_in[7];
    const float* decB1   = (const float*)d_in[8];
    const float* decW2   = (const float*)d_in[9];
    // d_in[10] dec_b2: drops out of softmax
    const float* decWih  = (const float*)d_in[11];
    const float* decWhh  = (const float*)d_in[12];
    const float* decBih  = (const float*)d_in[13];
    const float* decBhh  = (const float*)d_in[14];
    const float* fcW     = (const float*)d_in[15];
    const float* fcB     = (const float*)d_in[16];
    const float* fcfW    = (const float*)d_in[17];
    const float* fcfB    = (const float*)d_in[18];
    float* out = (float*)d_out;

    cudaFuncSetAttribute(enc_fused, cudaFuncAttributeMaxDynamicSharedMemorySize,
                         ENC_SMEM_FLOATS * 4);
    cudaFuncSetAttribute(dec_fused, cudaFuncAttributeMaxDynamicSharedMemorySize,
                         DEC_SMEM_FLOATS * 4);

    prep<<<964, 256>>>(encWih, encWhh, decWhh, decW1, encBih, encBhh, decBih, decBhh);
    calc_alpha<<<BB, 128>>>(X, encAttW);
    enc_fused<<<BB / 8, 1024, ENC_SMEM_FLOATS * 4>>>(X);
    gemm_preX<<<BB * TTT / 64, 256>>>(decB1);
    dec_fused<<<BB / 8, 1024, DEC_SMEM_FLOATS * 4>>>(decWih, decW2, fcW, fcB, fcfW, fcfB, out);
}